// round 13
// baseline (speedup 1.0000x reference)
#include <cuda_runtime.h>
#include <cuda_bf16.h>
#include <math.h>

#define BATCH 16
#define DIM 512
#define MIDC 32
#define NPIX 1024
#define NTOK 16384
#define FDIM 2048

typedef __nv_bfloat16 bf16;

// ---------------- scratch (static device memory) ----------------
__device__ bf16 g_xtok [NTOK * DIM];
__device__ bf16 g_xtok2[NTOK * DIM];
__device__ bf16 g_htok [NTOK * MIDC];
__device__ bf16 g_kwtok[NTOK * DIM];
__device__ bf16 g_y [BATCH * DIM * NPIX];
__device__ bf16 g_ybf[NTOK * DIM];
__device__ bf16 g_mid[NTOK * FDIM];
__device__ bf16 g_w1bf[FDIM * DIM];
__device__ bf16 g_w2bf[DIM * FDIM];
__device__ bf16 g_w1pe[9 * MIDC * DIM];
__device__ bf16 g_w1kg[9 * MIDC * DIM];
__device__ bf16 g_w2pe[9 * DIM * MIDC];
__device__ bf16 g_w2kg[9 * DIM * MIDC];

// ---------------- cp.async / ldmatrix helpers ----------------
__device__ __forceinline__ void cp16(void* s, const void* g) {
    unsigned sa = (unsigned)__cvta_generic_to_shared(s);
    asm volatile("cp.async.cg.shared.global [%0], [%1], 16;\n" :: "r"(sa), "l"(g));
}
__device__ __forceinline__ void cp16p(void* s, const void* g, bool pred) {
    unsigned sa = (unsigned)__cvta_generic_to_shared(s);
    int sz = pred ? 16 : 0;
    asm volatile("cp.async.cg.shared.global [%0], [%1], 16, %2;\n" :: "r"(sa), "l"(g), "r"(sz));
}
#define CP_COMMIT() asm volatile("cp.async.commit_group;\n")
#define CP_WAIT(n)  asm volatile("cp.async.wait_group %0;\n" :: "n"(n))

__device__ __forceinline__ void ldmx4(unsigned* r, const void* p) {
    unsigned a = (unsigned)__cvta_generic_to_shared(p);
    asm volatile("ldmatrix.sync.aligned.m8n8.x4.shared.b16 {%0,%1,%2,%3}, [%4];\n"
                 : "=r"(r[0]), "=r"(r[1]), "=r"(r[2]), "=r"(r[3]) : "r"(a));
}

// ---------------- merged weight conversion ----------------
__global__ void cvt_all(const float* __restrict__ w1, const float* __restrict__ w2,
                        const float* __restrict__ pw1, const float* __restrict__ kw1,
                        const float* __restrict__ pw2, const float* __restrict__ kw2,
                        bf16* __restrict__ o1, bf16* __restrict__ o2,
                        bf16* __restrict__ o1p, bf16* __restrict__ o1k,
                        bf16* __restrict__ o2p, bf16* __restrict__ o2k)
{
    int i = blockIdx.x * blockDim.x + threadIdx.x;
    if (i < FDIM * DIM) {
        o1[i] = __float2bfloat16(w1[i]);
        o2[i] = __float2bfloat16(w2[i]);
    }
    if (i < MIDC * DIM * 9) {
        int off = i % 9;
        int ic = (i / 9) % DIM, oc = i / (9 * DIM);
        o1p[(off * MIDC + oc) * DIM + ic] = __float2bfloat16(pw1[i]);
        o1k[(off * MIDC + oc) * DIM + ic] = __float2bfloat16(kw1[i]);
        int ic2 = (i / 9) % MIDC, oc2 = i / (9 * MIDC);
        o2p[(off * DIM + oc2) * MIDC + ic2] = __float2bfloat16(pw2[i]);
        o2k[(off * DIM + oc2) * MIDC + ic2] = __float2bfloat16(kw2[i]);
    }
}

// ---------------- NCHW fp32 -> token bf16 transpose ----------------
__global__ __launch_bounds__(256) void nchw2tok(const float* __restrict__ X, bf16* __restrict__ T)
{
    __shared__ bf16 sm[128][136];
    int hw0 = blockIdx.x * 128, c0 = blockIdx.y * 128, b = blockIdx.z;
    int tid = threadIdx.x;
    const float* xp = X + ((size_t)b * DIM + c0) * NPIX + hw0;
#pragma unroll
    for (int i = 0; i < 16; i++) {
        int idx = tid + i * 256;
        int rc = idx >> 5, u = idx & 31;
        float4 v = *(const float4*)&xp[(size_t)rc * NPIX + u * 4];
        union { uint2 q; bf16 h[4]; } pk;
        pk.h[0] = __float2bfloat16(v.x); pk.h[1] = __float2bfloat16(v.y);
        pk.h[2] = __float2bfloat16(v.z); pk.h[3] = __float2bfloat16(v.w);
        *(uint2*)&sm[rc][u * 4] = pk.q;
    }
    __syncthreads();
    bf16* tp = T + ((size_t)(b * NPIX + hw0)) * DIM + c0;
#pragma unroll
    for (int i = 0; i < 8; i++) {
        int idx = tid + i * 256;
        int rt = idx >> 4, uu = idx & 15;
        union { uint4 q; bf16 h[8]; } pk;
#pragma unroll
        for (int j = 0; j < 8; j++) pk.h[j] = sm[uu * 8 + j][rt];
        *(uint4*)&tp[(size_t)rt * DIM + uu * 8] = pk.q;
    }
}

// ---------------- MMA helper ----------------
__device__ __forceinline__ void mma16816(float* d, const unsigned* a, const unsigned* b) {
    asm volatile(
        "mma.sync.aligned.m16n8k16.row.col.f32.bf16.bf16.f32 "
        "{%0,%1,%2,%3}, {%4,%5,%6,%7}, {%8,%9}, {%0,%1,%2,%3};\n"
        : "+f"(d[0]), "+f"(d[1]), "+f"(d[2]), "+f"(d[3])
        : "r"(a[0]), "r"(a[1]), "r"(a[2]), "r"(a[3]), "r"(b[0]), "r"(b[1]));
}

// ---------------- conv1: 512-thread dual-warpgroup K-split -----------------
#define C1S 72
#define C1_AS_BYTES (6 * 64 * C1S * 2)
#define C1_BS_BYTES (6 * 32 * C1S * 2)
#define C1_PB_BYTES (8 * 16 * 16 * 4)
#define C1_SMEM (C1_AS_BYTES + C1_BS_BYTES + C1_PB_BYTES + 256)
__global__ __launch_bounds__(512) void conv1_tok(
    const bf16* __restrict__ X, const bf16* __restrict__ W,
    const float* __restrict__ bng, const float* __restrict__ bnb,
    const float* __restrict__ bnm, const float* __restrict__ bnv,
    bf16* __restrict__ O)
{
    extern __shared__ __align__(16) char dsm[];
    bf16 (*As)[64][C1S] = (bf16(*)[64][C1S])dsm;
    bf16 (*Bs)[32][C1S] = (bf16(*)[32][C1S])(dsm + C1_AS_BYTES);
    float (*pbuf)[16][16] = (float(*)[16][16])(dsm + C1_AS_BYTES + C1_BS_BYTES);
    float* sS = (float*)(dsm + C1_AS_BYTES + C1_BS_BYTES + C1_PB_BYTES);
    float* sT = sS + 32;

    int m0 = blockIdx.x * 64;
    int tid = threadIdx.x;
    if (tid < 32) {
        float inv = rsqrtf(bnv[tid] + 1e-5f);
        float s = bng[tid] * inv;
        sS[tid] = s;
        sT[tid] = bnb[tid] - bnm[tid] * s;
    }
    int ar = tid >> 3, aq = (tid & 7) * 16;
    int asub = aq >> 6, acol = aq & 63;
    int t = m0 + ar;
    int th = (t >> 5) & 31, tw = t & 31;
    int br = (tid & 255) >> 3, bq = (tid & 7) * 16;
    int bsub = bq >> 6, bcol = bq & 63;
    int wid = tid >> 5, lane = tid & 31;
    int wg = wid >> 3, wl = wid & 7;
    int wm = (wl & 3) * 16, wn = (wl >> 2) * 16;
    int g = lane >> 2, tg = lane & 3;
    int lrow = (lane & 7) + ((lane >> 3) & 1) * 8;
    int lcol = ((lane >> 4) & 1) * 8;

    float acc[2][4];
#pragma unroll
    for (int i = 0; i < 2; i++)
#pragma unroll
        for (int j = 0; j < 4; j++) acc[i][j] = 0.f;

    auto load_pair = [&](int p, int ds) {
        int off = p >> 2, k0 = (p & 3) * 128;
        int dy = off / 3 - 1, dx = off % 3 - 1;
        bool valid = ((unsigned)(th + dy) < 32u) && ((unsigned)(tw + dx) < 32u);
        const bf16* srcA = X + ((long)(t + dy * 32 + dx)) * DIM + k0 + aq;
        cp16p(&As[ds * 2 + asub][ar][acol],     srcA,     valid);
        cp16p(&As[ds * 2 + asub][ar][acol + 8], srcA + 8, valid);
        if (tid < 256) {
            const bf16* srcB = W + (size_t)(off * MIDC + br) * DIM + k0 + bq;
            cp16(&Bs[ds * 2 + bsub][br][bcol],     srcB);
            cp16(&Bs[ds * 2 + bsub][br][bcol + 8], srcB + 8);
        }
    };

    load_pair(0, 0);
    CP_COMMIT();
    load_pair(1, 1);
    CP_COMMIT();
    for (int p = 0; p < 36; p++) {
        int ds = p % 3;
        if (p + 1 < 36) { CP_WAIT(1); } else { CP_WAIT(0); }
        __syncthreads();
        if (p + 2 < 36) {
            load_pair(p + 2, (p + 2) % 3);
            CP_COMMIT();
        }
        int buf = ds * 2 + wg;
#pragma unroll
        for (int kc = 0; kc < 4; kc++) {
            int kb = kc * 16;
            unsigned a[4], bb[4];
            ldmx4(a,  &As[buf][wm + lrow][kb + lcol]);
            ldmx4(bb, &Bs[buf][wn + lrow][kb + lcol]);
            unsigned b0[2] = { bb[0], bb[2] };
            unsigned b1[2] = { bb[1], bb[3] };
            mma16816(acc[0], a, b0);
            mma16816(acc[1], a, b1);
        }
    }
    if (wg == 1) {
#pragma unroll
        for (int ni = 0; ni < 2; ni++)
#pragma unroll
            for (int rr = 0; rr < 2; rr++)
#pragma unroll
                for (int j = 0; j < 2; j++)
                    pbuf[wl][g + rr * 8][ni * 8 + tg * 2 + j] = acc[ni][rr * 2 + j];
    }
    __syncthreads();
    if (wg == 0) {
#pragma unroll
        for (int ni = 0; ni < 2; ni++)
#pragma unroll
            for (int rr = 0; rr < 2; rr++) {
                int col = wn + ni * 8 + tg * 2;
                int row = wm + g + rr * 8;
                float v0 = acc[ni][rr * 2 + 0] + pbuf[wl][g + rr * 8][ni * 8 + tg * 2 + 0];
                float v1 = acc[ni][rr * 2 + 1] + pbuf[wl][g + rr * 8][ni * 8 + tg * 2 + 1];
                v0 = fmaxf(v0 * sS[col]     + sT[col],     0.f);
                v1 = fmaxf(v1 * sS[col + 1] + sT[col + 1], 0.f);
                __nv_bfloat162 pk;
                pk.x = __float2bfloat16(v0);
                pk.y = __float2bfloat16(v1);
                *(__nv_bfloat162*)&O[(size_t)(m0 + row) * MIDC + col] = pk;
            }
    }
}

// ---------------- conv2: halo-resident, barrier-free mainloop ---------------
#define C2_HS_BYTES (6 * 34 * 40 * 2)
#define C2_BS_BYTES (9 * 64 * 40 * 2)
#define C2_SMEM (C2_HS_BYTES + C2_BS_BYTES + 128)
__global__ __launch_bounds__(256) void conv2_tok(
    const bf16* __restrict__ Hx, const bf16* __restrict__ W,
    const float* __restrict__ b2, const bf16* __restrict__ res,
    bf16* __restrict__ O)
{
    extern __shared__ __align__(16) char dsm2[];
    bf16 (*hs)[34][40] = (bf16(*)[34][40])dsm2;
    bf16 (*bs)[64][40] = (bf16(*)[64][40])(dsm2 + C2_HS_BYTES);
    int n0 = blockIdx.x * 64, m0 = blockIdx.y * 128;
    int b = m0 >> 10;
    int row0 = (m0 >> 5) & 31;
    int tid = threadIdx.x;

    for (int idx = tid; idx < 816; idx += 256) {
        int pos = idx >> 2, chk = idx & 3;
        int r = pos / 34, c = pos - r * 34;
        int trow = row0 + r - 1, tcol = c - 1;
        bool valid = ((unsigned)trow < 32u) && ((unsigned)tcol < 32u);
        const bf16* src = Hx + ((size_t)(b * NPIX + trow * 32 + tcol)) * MIDC + chk * 8;
        cp16p(&hs[r][c][chk * 8], src, valid);
    }
    {
        int row = tid >> 2, chk = tid & 3;
#pragma unroll
        for (int off = 0; off < 9; off++)
            cp16(&bs[off][row][chk * 8],
                 &W[(size_t)(off * DIM + n0 + row) * MIDC + chk * 8]);
    }
    CP_COMMIT();
    CP_WAIT(0);
    __syncthreads();

    int wid = tid >> 5, lane = tid & 31;
    int wm = (wid & 3) * 32, wn = (wid >> 2) * 32;
    int g = lane >> 2, tg = lane & 3;
    int lrow = (lane & 7) + ((lane >> 3) & 1) * 8;
    int lcol = ((lane >> 4) & 1) * 8;

    float acc[2][4][4];
#pragma unroll
    for (int i = 0; i < 2; i++)
#pragma unroll
        for (int j = 0; j < 4; j++)
#pragma unroll
            for (int k = 0; k < 4; k++) acc[i][j][k] = 0.f;

    const bf16* abase[2];
#pragma unroll
    for (int mi = 0; mi < 2; mi++) {
        int tok = wm + mi * 16 + lrow;
        int tr = tok >> 5, tc = tok & 31;
        abase[mi] = &hs[tr + 1][tc + 1][lcol];
    }

#pragma unroll
    for (int off = 0; off < 9; off++) {
        int dy = off / 3 - 1, dx = off % 3 - 1;
        int shift = (dy * 34 + dx) * 40;
#pragma unroll
        for (int kc = 0; kc < 2; kc++) {
            int kb = kc * 16;
            unsigned a[2][4], bb[2][4];
#pragma unroll
            for (int mi = 0; mi < 2; mi++)
                ldmx4(a[mi], abase[mi] + shift + kb);
#pragma unroll
            for (int nh = 0; nh < 2; nh++)
                ldmx4(bb[nh], &bs[off][wn + nh * 16 + lrow][kb + lcol]);
#pragma unroll
            for (int mi = 0; mi < 2; mi++)
#pragma unroll
                for (int ni = 0; ni < 4; ni++) {
                    unsigned bfr[2] = { bb[ni >> 1][ni & 1], bb[ni >> 1][(ni & 1) + 2] };
                    mma16816(acc[mi][ni], a[mi], bfr);
                }
        }
    }
    float bv0[4], bv1[4];
#pragma unroll
    for (int ni = 0; ni < 4; ni++) {
        int col = n0 + wn + ni * 8 + tg * 2;
        bv0[ni] = b2[col];
        bv1[ni] = b2[col + 1];
    }
#pragma unroll
    for (int mi = 0; mi < 2; mi++)
#pragma unroll
        for (int ni = 0; ni < 4; ni++)
#pragma unroll
            for (int rr = 0; rr < 2; rr++) {
                int row = m0 + wm + mi * 16 + g + rr * 8;
                size_t ad = (size_t)row * DIM + n0 + wn + ni * 8 + tg * 2;
                float v0 = acc[mi][ni][rr * 2 + 0] + bv0[ni];
                float v1 = acc[mi][ni][rr * 2 + 1] + bv1[ni];
                if (res) {
                    __nv_bfloat162 rv = *(const __nv_bfloat162*)&res[ad];
                    v0 += __bfloat162float(rv.x);
                    v1 += __bfloat162float(rv.y);
                }
                __nv_bfloat162 p;
                p.x = __float2bfloat16(v0);
                p.y = __float2bfloat16(v1);
                *(__nv_bfloat162*)&O[ad] = p;
            }
}

// ---------------- circ: reads tokens, computes means, writes bf16 y ---------
__global__ __launch_bounds__(256) void circ_tok(
    const bf16* __restrict__ Xt, const bf16* __restrict__ KWt,
    const float* __restrict__ bias, bf16* __restrict__ y)
{
    __shared__ float xs[4][32][36];
    __shared__ float ks[4][32][36];
    __shared__ float kv[4][32];
    int p0 = blockIdx.x * 4;
    int b = p0 >> 9;
    int c0 = p0 & 511;
    int tid = threadIdx.x;
    int lp = tid >> 6, lt = tid & 63;
    int c = c0 + lp;

#pragma unroll
    for (int i = 0; i < 4; i++) {
        int tok = tid + i * 256;
        int hh = tok >> 5, ww = tok & 31;
        size_t base = (size_t)(b * NPIX + tok) * DIM + c0;
        uint2 xv = *(const uint2*)&Xt[base];
        uint2 kw = *(const uint2*)&KWt[base];
        const __nv_bfloat162* xh = (const __nv_bfloat162*)&xv;
        const __nv_bfloat162* kh = (const __nv_bfloat162*)&kw;
        xs[0][hh][ww] = __bfloat162float(xh[0].x);
        xs[1][hh][ww] = __bfloat162float(xh[0].y);
        xs[2][hh][ww] = __bfloat162float(xh[1].x);
        xs[3][hh][ww] = __bfloat162float(xh[1].y);
        ks[0][hh][ww] = __bfloat162float(kh[0].x);
        ks[1][hh][ww] = __bfloat162float(kh[0].y);
        ks[2][hh][ww] = __bfloat162float(kh[1].x);
        ks[3][hh][ww] = __bfloat162float(kh[1].y);
    }
    __syncthreads();
    if (lt < 32) {
        float s = 0.f;
        if (c < 256) {
#pragma unroll
            for (int ww = 0; ww < 32; ww++) s += ks[lp][lt][ww];
        } else {
#pragma unroll
            for (int hh = 0; hh < 32; hh++) s += ks[lp][hh][lt];
        }
        kv[lp][lt] = s * (1.f / 32.f);
    }
    __syncthreads();

    int t_r = (lt >> 3) * 4;
    int t_c = (lt & 7) * 4;
    float acc[4][4];
#pragma unroll
    for (int r = 0; r < 4; r++)
#pragma unroll
        for (int cc2 = 0; cc2 < 4; cc2++) acc[r][cc2] = 0.f;
    float bv = bias[c];

    if (c < 256) {
        float kr[32];
#pragma unroll
        for (int u = 0; u < 32; u++) kr[u] = kv[lp][(u - t_r) & 31];
#pragma unroll
        for (int j = 0; j < 32; j++) {
            float4 xv = *(const float4*)&xs[lp][j][t_c];
#pragma unroll
            for (int ri = 0; ri < 4; ri++) {
                float kk = kr[(j - ri) & 31];
                acc[ri][0] += kk * xv.x;
                acc[ri][1] += kk * xv.y;
                acc[ri][2] += kk * xv.z;
                acc[ri][3] += kk * xv.w;
            }
        }
    } else {
        float kr[32];
#pragma unroll
        for (int u = 0; u < 32; u++) kr[u] = kv[lp][(u - t_c) & 31];
#pragma unroll
        for (int j = 0; j < 32; j++) {
            float xv[4];
#pragma unroll
            for (int ri = 0; ri < 4; ri++) xv[ri] = xs[lp][t_r + ri][j];
#pragma unroll
            for (int ci = 0; ci < 4; ci++) {
                float kk = kr[(j - ci) & 31];
#pragma unroll
                for (int ri = 0; ri < 4; ri++) acc[ri][ci] += kk * xv[ri];
            }
        }
    }
    bf16* yp = y + (size_t)(p0 + lp) * NPIX;
#pragma unroll
    for (int ri = 0; ri < 4; ri++) {
        union { uint2 q; bf16 h[4]; } pk;
        pk.h[0] = __float2bfloat16(acc[ri][0] + bv);
        pk.h[1] = __float2bfloat16(acc[ri][1] + bv);
        pk.h[2] = __float2bfloat16(acc[ri][2] + bv);
        pk.h[3] = __float2bfloat16(acc[ri][3] + bv);
        *(uint2*)&yp[(t_r + ri) * 32 + t_c] = pk.q;
    }
}

// ---------------- LayerNorm: bf16 NCHW in, bf16 tokens out ------------------
__global__ __launch_bounds__(256) void ln2_kernel(
    const bf16* __restrict__ Y, const float* __restrict__ lnw,
    const float* __restrict__ lnb, bf16* __restrict__ O)
{
    __shared__ float red[256], red2[256];
    __shared__ float mus[64], rss[64];
    int chunk = blockIdx.x, b = blockIdx.y;
    int hw0 = chunk * 64;
    int tid = threadIdx.x;
    int j = tid & 63, q = tid >> 6;
    const bf16* yb = Y + (size_t)b * DIM * NPIX + hw0 + j;
    float s = 0.f, s2 = 0.f;
    for (int c = q * 128; c < q * 128 + 128; c++) {
        float v = __bfloat162float(yb[(size_t)c * NPIX]);
        s += v; s2 += v * v;
    }
    red[tid] = s; red2[tid] = s2;
    __syncthreads();
    if (tid < 64) {
        float S = red[tid] + red[tid + 64] + red[tid + 128] + red[tid + 192];
        float S2 = red2[tid] + red2[tid + 64] + red2[tid + 128] + red2[tid + 192];
        float mu = S * (1.f / 512.f);
        float var = S2 * (1.f / 512.f) - mu * mu;
        mus[tid] = mu;
        rss[tid] = rsqrtf(var + 1e-6f);
    }
    __syncthreads();
    float mu = mus[j], rstd = rss[j];
    size_t t0 = (size_t)b * NPIX + hw0;
    for (int c8 = q * 128; c8 < q * 128 + 128; c8 += 8) {
        union { uint4 u; bf16 h[8]; } pk;
#pragma unroll
        for (int i = 0; i < 8; i++) {
            int c = c8 + i;
            float v = __bfloat162float(yb[(size_t)c * NPIX]);
            pk.h[i] = __float2bfloat16((v - mu) * rstd * __ldg(&lnw[c]) + __ldg(&lnb[c]));
        }
        *(uint4*)&O[(t0 + j) * DIM + c8] = pk.u;
    }
}

__device__ __forceinline__ float gelu_exact(float x) {
    return 0.5f * x * (1.f + erff(x * 0.70710678118654752f));
}

// ---------------- MLP GEMMs: BM=256, BN=128, BK=64, 512 threads -------------
#define GBM 256
#define GBN 128
#define GS 72
#define G_AS_BYTES (3 * GBM * GS * 2)       // 110592
#define G_BS_BYTES (3 * GBN * GS * 2)       // 55296
#define G_SMEM (G_AS_BYTES + G_BS_BYTES)    // 165888

// GEMM1: C[16384,2048] = gelu(A[16384,512] * W1[2048,512]^T + b)
__global__ __launch_bounds__(512) void gemm1_gelu(
    const bf16* __restrict__ A, const bf16* __restrict__ Bw,
    const float* __restrict__ bias, bf16* __restrict__ C)
{
    const int K = DIM, KT = K / 64;
    extern __shared__ __align__(16) char dsg1[];
    bf16 (*As)[GBM][GS] = (bf16(*)[GBM][GS])dsg1;
    bf16 (*Bs)[GBN][GS] = (bf16(*)[GBN][GS])(dsg1 + G_AS_BYTES);
    int m0 = blockIdx.y * GBM, n0 = blockIdx.x * GBN;
    int tid = threadIdx.x;
    int wid = tid >> 5, lane = tid & 31;
    int wm = (wid & 3) * 64, wn = (wid >> 2) * 32;
    int g = lane >> 2, tg = lane & 3;
    int lrow = (lane & 7) + ((lane >> 3) & 1) * 8;
    int lcol = ((lane >> 4) & 1) * 8;
    float acc[4][4][4];
#pragma unroll
    for (int i = 0; i < 4; i++)
#pragma unroll
        for (int j = 0; j < 4; j++)
#pragma unroll
            for (int k = 0; k < 4; k++) acc[i][j][k] = 0.f;

    int lr = tid >> 1, lc = (tid & 1) * 32;   // A: 256 rows, 2 half-rows of 32
    const bf16* apb = &A[(size_t)(m0 + lr) * K + lc];
    const bf16* bpb = &Bw[(size_t)(n0 + lr) * K + lc];   // valid for tid<256

    auto load_tile = [&](int kt, int buf) {
        const bf16* ap = apb + kt * 64;
        cp16(&As[buf][lr][lc],      ap);
        cp16(&As[buf][lr][lc + 8],  ap + 8);
        cp16(&As[buf][lr][lc + 16], ap + 16);
        cp16(&As[buf][lr][lc + 24], ap + 24);
        if (tid < 256) {
            const bf16* bp = bpb + kt * 64;
            cp16(&Bs[buf][lr][lc],      bp);
            cp16(&Bs[buf][lr][lc + 8],  bp + 8);
            cp16(&Bs[buf][lr][lc + 16], bp + 16);
            cp16(&Bs[buf][lr][lc + 24], bp + 24);
        }
    };

    load_tile(0, 0);
    CP_COMMIT();
    load_tile(1, 1);
    CP_COMMIT();
    for (int kt = 0; kt < KT; kt++) {
        int buf = kt % 3;
        if (kt + 1 < KT) { CP_WAIT(1); } else { CP_WAIT(0); }
        __syncthreads();
        if (kt + 2 < KT) {
            load_tile(kt + 2, (kt + 2) % 3);
            CP_COMMIT();
        }
#pragma unroll
        for (int ks = 0; ks < 4; ks++) {
            int kb = ks * 16;
            unsigned af[4][4], bb[2][4];
#pragma unroll
            for (int mi = 0; mi < 4; mi++)
                ldmx4(af[mi], &As[buf][wm + mi * 16 + lrow][kb + lcol]);
#pragma unroll
            for (int nh = 0; nh < 2; nh++)
                ldmx4(bb[nh], &Bs[buf][wn + nh * 16 + lrow][kb + lcol]);
#pragma unroll
            for (int mi = 0; mi < 4; mi++)
#pragma unroll
                for (int ni = 0; ni < 4; ni++) {
                    unsigned bfr[2] = { bb[ni >> 1][ni & 1], bb[ni >> 1][(ni & 1) + 2] };
                    mma16816(acc[mi][ni], af[mi], bfr);
                }
        }
    }
#pragma unroll
    for (int mi = 0; mi < 4; mi++)
#pragma unroll
        for (int ni = 0; ni < 4; ni++) {
            int col = n0 + wn + ni * 8 + tg * 2;
            float b0 = bias[col], b1 = bias[col + 1];
            int row0 = m0 + wm + mi * 16 + g;
#pragma unroll
            for (int rr = 0; rr < 2; rr++) {
                int r = row0 + rr * 8;
                float v0 = gelu_exact(acc[mi][ni][rr * 2 + 0] + b0);
                float v1 = gelu_exact(acc[mi][ni][rr * 2 + 1] + b1);
                __nv_bfloat162 p;
                p.x = __float2bfloat16(v0);
                p.y = __float2bfloat16(v1);
                *(__nv_bfloat162*)&C[(size_t)r * FDIM + col] = p;
            }
        }
}

// GEMM2: out = x_in + gamma*(A[16384,2048]*W2[512,2048]^T + b), NCHW epilogue
__global__ __launch_bounds__(512) void gemm2_res(
    const bf16* __restrict__ A, const bf16* __restrict__ Bw,
    const float* __restrict__ bias2, const float* __restrict__ gamma,
    const float* __restrict__ xin, float* __restrict__ out)
{
    const int K = FDIM, KT = K / 64;
    extern __shared__ __align__(16) char dsg2[];
    bf16 (*As)[GBM][GS] = (bf16(*)[GBM][GS])dsg2;
    bf16 (*Bs)[GBN][GS] = (bf16(*)[GBN][GS])(dsg2 + G_AS_BYTES);
    int m0 = blockIdx.y * GBM, n0 = blockIdx.x * GBN;
    int tid = threadIdx.x;
    int wid = tid >> 5, lane = tid & 31;
    int wm = (wid & 3) * 64, wn = (wid >> 2) * 32;
    int g = lane >> 2, tg = lane & 3;
    int lrow = (lane & 7) + ((lane >> 3) & 1) * 8;
    int lcol = ((lane >> 4) & 1) * 8;
    float acc[4][4][4];
#pragma unroll
    for (int i = 0; i < 4; i++)
#pragma unroll
        for (int j = 0; j < 4; j++)
#pragma unroll
            for (int k = 0; k < 4; k++) acc[i][j][k] = 0.f;

    int lr = tid >> 1, lc = (tid & 1) * 32;
    const bf16* apb = &A[(size_t)(m0 + lr) * K + lc];
    const bf16* bpb = &Bw[(size_t)(n0 + lr) * K + lc];

    auto load_tile = [&](int kt, int buf) {
        const bf16* ap = apb + kt * 64;
        cp16(&As[buf][lr][lc],      ap);
        cp16(&As[buf][lr][lc + 8],  ap + 8);
        cp16(&As[buf][lr][lc + 16], ap + 16);
        cp16(&As[buf][lr][lc + 24], ap + 24);
        if (tid < 256) {
            const bf16* bp = bpb + kt * 64;
            cp16(&Bs[buf][lr][lc],      bp);
            cp16(&Bs[buf][lr][lc + 8],  bp + 8);
            cp16(&Bs[buf][lr][lc + 16], bp + 16);
            cp16(&Bs[buf][lr][lc + 24], bp + 24);
        }
    };

    load_tile(0, 0);
    CP_COMMIT();
    load_tile(1, 1);
    CP_COMMIT();
    for (int kt = 0; kt < KT; kt++) {
        int buf = kt % 3;
        if (kt + 1 < KT) { CP_WAIT(1); } else { CP_WAIT(0); }
        __syncthreads();
        if (kt + 2 < KT) {
            load_tile(kt + 2, (kt + 2) % 3);
            CP_COMMIT();
        }
#pragma unroll
        for (int ks = 0; ks < 4; ks++) {
            int kb = ks * 16;
            unsigned af[4][4], bb[2][4];
#pragma unroll
            for (int mi = 0; mi < 4; mi++)
                ldmx4(af[mi], &As[buf][wm + mi * 16 + lrow][kb + lcol]);
#pragma unroll
            for (int nh = 0; nh < 2; nh++)
                ldmx4(bb[nh], &Bs[buf][wn + nh * 16 + lrow][kb + lcol]);
#pragma unroll
            for (int mi = 0; mi < 4; mi++)
#pragma unroll
                for (int ni = 0; ni < 4; ni++) {
                    unsigned bfr[2] = { bb[ni >> 1][ni & 1], bb[ni >> 1][(ni & 1) + 2] };
                    mma16816(acc[mi][ni], af[mi], bfr);
                }
        }
    }
    __syncthreads();
    // epilogue: 32-col chunks through smem (256 rows) -> coalesced NCHW writes
    float (*sbuf)[33] = (float(*)[33])dsg2;
    int cc = tid >> 4, seg = tid & 15;
#pragma unroll
    for (int nc = 0; nc < 4; nc++) {
        if ((wid >> 2) == nc) {
#pragma unroll
            for (int mi = 0; mi < 4; mi++)
#pragma unroll
                for (int ni = 0; ni < 4; ni++)
#pragma unroll
                    for (int rr = 0; rr < 2; rr++)
#pragma unroll
                        for (int j = 0; j < 2; j++)
                            sbuf[wm + mi * 16 + g + rr * 8][ni * 8 + tg * 2 + j] =
                                acc[mi][ni][rr * 2 + j];
        }
        __syncthreads();
        int col = n0 + nc * 32 + cc;
        float gb = gamma[col], bb2 = bias2[col];
        size_t colbase = ((size_t)(m0 >> 10) * DIM + col) * NPIX + (m0 & 1023);
#pragma unroll
        for (int q = 0; q < 4; q++) {
            int r = q * 64 + seg * 4;
            float4 xv = *(const float4*)&xin[colbase + r];
            float4 o;
            o.x = xv.x + gb * (sbuf[r + 0][cc] + bb2);
            o.y = xv.y + gb * (sbuf[r + 1][cc] + bb2);
            o.z = xv.z + gb * (sbuf[r + 2][cc] + bb2);
            o.w = xv.w + gb * (sbuf[r + 3][cc] + bb2);
            *(float4*)&out[colbase + r] = o;
        }
        __syncthreads();
    }
}

// ---------------- host launcher ----------------
extern "C" void kernel_launch(void* const* d_in, const int* in_sizes, int n_in,
                              void* d_out, int out_size)
{
    const float* x      = (const float*)d_in[0];
    const float* pe_w1  = (const float*)d_in[1];
    const float* pe_bng = (const float*)d_in[2];
    const float* pe_bnb = (const float*)d_in[3];
    const float* pe_bnm = (const float*)d_in[4];
    const float* pe_bnv = (const float*)d_in[5];
    const float* pe_w2  = (const float*)d_in[6];
    const float* pe_b2  = (const float*)d_in[7];
    const float* kg_w1  = (const float*)d_in[8];
    const float* kg_bng = (const float*)d_in[9];
    const float* kg_bnb = (const float*)d_in[10];
    const float* kg_bnm = (const float*)d_in[11];
    const float* kg_bnv = (const float*)d_in[12];
    const float* kg_w2  = (const float*)d_in[13];
    const float* kg_b2  = (const float*)d_in[14];
    const float* bias   = (const float*)d_in[15];
    const float* ln_w   = (const float*)d_in[16];
    const float* ln_b   = (const float*)d_in[17];
    const float* pw1_w  = (const float*)d_in[18];
    const float* pw1_b  = (const float*)d_in[19];
    const float* pw2_w  = (const float*)d_in[20];
    const float* pw2_b  = (const float*)d_in[21];
    const float* gamma  = (const float*)d_in[22];
    float* outp = (float*)d_out;

    bf16 *pxtok, *pxtok2, *phtok, *pkwtok, *pybf, *pmid, *pw1bf, *pw2bf;
    bf16 *pw1pe, *pw1kg, *pw2pe, *pw2kg, *py;
    cudaGetSymbolAddress((void**)&pxtok,  g_xtok);
    cudaGetSymbolAddress((void**)&pxtok2, g_xtok2);
    cudaGetSymbolAddress((void**)&phtok,  g_htok);
    cudaGetSymbolAddress((void**)&pkwtok, g_kwtok);
    cudaGetSymbolAddress((void**)&py,  g_y);
    cudaGetSymbolAddress((void**)&pybf,  g_ybf);
    cudaGetSymbolAddress((void**)&pmid,  g_mid);
    cudaGetSymbolAddress((void**)&pw1bf, g_w1bf);
    cudaGetSymbolAddress((void**)&pw2bf, g_w2bf);
    cudaGetSymbolAddress((void**)&pw1pe, g_w1pe);
    cudaGetSymbolAddress((void**)&pw1kg, g_w1kg);
    cudaGetSymbolAddress((void**)&pw2pe, g_w2pe);
    cudaGetSymbolAddress((void**)&pw2kg, g_w2kg);

    cudaFuncSetAttribute(conv1_tok, cudaFuncAttributeMaxDynamicSharedMemorySize, C1_SMEM);
    cudaFuncSetAttribute(conv2_tok, cudaFuncAttributeMaxDynamicSharedMemorySize, C2_SMEM);
    cudaFuncSetAttribute(gemm1_gelu, cudaFuncAttributeMaxDynamicSharedMemorySize, G_SMEM);
    cudaFuncSetAttribute(gemm2_res, cudaFuncAttributeMaxDynamicSharedMemorySize, G_SMEM);

    cvt_all<<<(FDIM * DIM + 255) / 256, 256>>>(pw1_w, pw2_w, pe_w1, kg_w1, pe_w2, kg_w2,
                                               pw1bf, pw2bf, pw1pe, pw1kg, pw2pe, pw2kg);
    nchw2tok<<<dim3(8, 4, BATCH), 256>>>(x, pxtok);

    conv1_tok<<<NTOK / 64, 512, C1_SMEM>>>(pxtok, pw1pe, pe_bng, pe_bnb, pe_bnm, pe_bnv, phtok);
    conv2_tok<<<dim3(8, NTOK / 128), 256, C2_SMEM>>>(phtok, pw2pe, pe_b2, pxtok, pxtok2);
    conv1_tok<<<NTOK / 64, 512, C1_SMEM>>>(pxtok2, pw1kg, kg_bng, kg_bnb, kg_bnm, kg_bnv, phtok);
    conv2_tok<<<dim3(8, NTOK / 128), 256, C2_SMEM>>>(phtok, pw2kg, kg_b2, nullptr, pkwtok);

    circ_tok<<<(BATCH * DIM) / 4, 256>>>(pxtok2, pkwtok, bias, py);

    ln2_kernel<<<dim3(16, BATCH), 256>>>(py, ln_w, ln_b, pybf);

    gemm1_gelu<<<dim3(FDIM / GBN, NTOK / GBM), 512, G_SMEM>>>(pybf, pw1bf, pw1_b, pmid);
    gemm2_res<<<dim3(DIM / GBN, NTOK / GBM), 512, G_SMEM>>>(pmid, pw2bf, pw2_b, gamma, x, outp);
}

// round 14
// speedup vs baseline: 1.0598x; 1.0598x over previous
#include <cuda_runtime.h>
#include <cuda_bf16.h>
#include <math.h>

#define BATCH 16
#define DIM 512
#define MIDC 32
#define NPIX 1024
#define NTOK 16384
#define FDIM 2048

typedef __nv_bfloat16 bf16;

// ---------------- scratch (static device memory) ----------------
__device__ bf16 g_xtok [NTOK * DIM];
__device__ bf16 g_xtok2[NTOK * DIM];
__device__ bf16 g_htok [NTOK * MIDC];
__device__ bf16 g_kwtok[NTOK * DIM];
__device__ bf16 g_y [BATCH * DIM * NPIX];
__device__ bf16 g_ybf[NTOK * DIM];
__device__ bf16 g_mid[NTOK * FDIM];
__device__ bf16 g_w1bf[FDIM * DIM];
__device__ bf16 g_w2bf[DIM * FDIM];
__device__ bf16 g_w1pe[9 * MIDC * DIM];
__device__ bf16 g_w1kg[9 * MIDC * DIM];
__device__ bf16 g_w2pe[9 * DIM * MIDC];
__device__ bf16 g_w2kg[9 * DIM * MIDC];

// ---------------- cp.async / ldmatrix helpers ----------------
__device__ __forceinline__ void cp16(void* s, const void* g) {
    unsigned sa = (unsigned)__cvta_generic_to_shared(s);
    asm volatile("cp.async.cg.shared.global [%0], [%1], 16;\n" :: "r"(sa), "l"(g));
}
__device__ __forceinline__ void cp16p(void* s, const void* g, bool pred) {
    unsigned sa = (unsigned)__cvta_generic_to_shared(s);
    int sz = pred ? 16 : 0;
    asm volatile("cp.async.cg.shared.global [%0], [%1], 16, %2;\n" :: "r"(sa), "l"(g), "r"(sz));
}
#define CP_COMMIT() asm volatile("cp.async.commit_group;\n")
#define CP_WAIT(n)  asm volatile("cp.async.wait_group %0;\n" :: "n"(n))

__device__ __forceinline__ void ldmx4(unsigned* r, const void* p) {
    unsigned a = (unsigned)__cvta_generic_to_shared(p);
    asm volatile("ldmatrix.sync.aligned.m8n8.x4.shared.b16 {%0,%1,%2,%3}, [%4];\n"
                 : "=r"(r[0]), "=r"(r[1]), "=r"(r[2]), "=r"(r[3]) : "r"(a));
}

// ---------------- merged weight conversion ----------------
__global__ void cvt_all(const float* __restrict__ w1, const float* __restrict__ w2,
                        const float* __restrict__ pw1, const float* __restrict__ kw1,
                        const float* __restrict__ pw2, const float* __restrict__ kw2,
                        bf16* __restrict__ o1, bf16* __restrict__ o2,
                        bf16* __restrict__ o1p, bf16* __restrict__ o1k,
                        bf16* __restrict__ o2p, bf16* __restrict__ o2k)
{
    int i = blockIdx.x * blockDim.x + threadIdx.x;
    if (i < FDIM * DIM) {
        o1[i] = __float2bfloat16(w1[i]);
        o2[i] = __float2bfloat16(w2[i]);
    }
    if (i < MIDC * DIM * 9) {
        int off = i % 9;
        int ic = (i / 9) % DIM, oc = i / (9 * DIM);
        o1p[(off * MIDC + oc) * DIM + ic] = __float2bfloat16(pw1[i]);
        o1k[(off * MIDC + oc) * DIM + ic] = __float2bfloat16(kw1[i]);
        int ic2 = (i / 9) % MIDC, oc2 = i / (9 * MIDC);
        o2p[(off * DIM + oc2) * MIDC + ic2] = __float2bfloat16(pw2[i]);
        o2k[(off * DIM + oc2) * MIDC + ic2] = __float2bfloat16(kw2[i]);
    }
}

// ---------------- NCHW fp32 -> token bf16 transpose ----------------
__global__ __launch_bounds__(256) void nchw2tok(const float* __restrict__ X, bf16* __restrict__ T)
{
    __shared__ bf16 sm[128][136];
    int hw0 = blockIdx.x * 128, c0 = blockIdx.y * 128, b = blockIdx.z;
    int tid = threadIdx.x;
    const float* xp = X + ((size_t)b * DIM + c0) * NPIX + hw0;
#pragma unroll
    for (int i = 0; i < 16; i++) {
        int idx = tid + i * 256;
        int rc = idx >> 5, u = idx & 31;
        float4 v = *(const float4*)&xp[(size_t)rc * NPIX + u * 4];
        union { uint2 q; bf16 h[4]; } pk;
        pk.h[0] = __float2bfloat16(v.x); pk.h[1] = __float2bfloat16(v.y);
        pk.h[2] = __float2bfloat16(v.z); pk.h[3] = __float2bfloat16(v.w);
        *(uint2*)&sm[rc][u * 4] = pk.q;
    }
    __syncthreads();
    bf16* tp = T + ((size_t)(b * NPIX + hw0)) * DIM + c0;
#pragma unroll
    for (int i = 0; i < 8; i++) {
        int idx = tid + i * 256;
        int rt = idx >> 4, uu = idx & 15;
        union { uint4 q; bf16 h[8]; } pk;
#pragma unroll
        for (int j = 0; j < 8; j++) pk.h[j] = sm[uu * 8 + j][rt];
        *(uint4*)&tp[(size_t)rt * DIM + uu * 8] = pk.q;
    }
}

// ---------------- MMA helper ----------------
__device__ __forceinline__ void mma16816(float* d, const unsigned* a, const unsigned* b) {
    asm volatile(
        "mma.sync.aligned.m16n8k16.row.col.f32.bf16.bf16.f32 "
        "{%0,%1,%2,%3}, {%4,%5,%6,%7}, {%8,%9}, {%0,%1,%2,%3};\n"
        : "+f"(d[0]), "+f"(d[1]), "+f"(d[2]), "+f"(d[3])
        : "r"(a[0]), "r"(a[1]), "r"(a[2]), "r"(a[3]), "r"(b[0]), "r"(b[1]));
}

// ---------------- conv1: 512-thread dual-warpgroup K-split -----------------
#define C1S 72
#define C1_AS_BYTES (6 * 64 * C1S * 2)
#define C1_BS_BYTES (6 * 32 * C1S * 2)
#define C1_PB_BYTES (8 * 16 * 16 * 4)
#define C1_SMEM (C1_AS_BYTES + C1_BS_BYTES + C1_PB_BYTES + 256)
__global__ __launch_bounds__(512) void conv1_tok(
    const bf16* __restrict__ X, const bf16* __restrict__ W,
    const float* __restrict__ bng, const float* __restrict__ bnb,
    const float* __restrict__ bnm, const float* __restrict__ bnv,
    bf16* __restrict__ O)
{
    extern __shared__ __align__(16) char dsm[];
    bf16 (*As)[64][C1S] = (bf16(*)[64][C1S])dsm;
    bf16 (*Bs)[32][C1S] = (bf16(*)[32][C1S])(dsm + C1_AS_BYTES);
    float (*pbuf)[16][16] = (float(*)[16][16])(dsm + C1_AS_BYTES + C1_BS_BYTES);
    float* sS = (float*)(dsm + C1_AS_BYTES + C1_BS_BYTES + C1_PB_BYTES);
    float* sT = sS + 32;

    int m0 = blockIdx.x * 64;
    int tid = threadIdx.x;
    if (tid < 32) {
        float inv = rsqrtf(bnv[tid] + 1e-5f);
        float s = bng[tid] * inv;
        sS[tid] = s;
        sT[tid] = bnb[tid] - bnm[tid] * s;
    }
    int ar = tid >> 3, aq = (tid & 7) * 16;
    int asub = aq >> 6, acol = aq & 63;
    int t = m0 + ar;
    int th = (t >> 5) & 31, tw = t & 31;
    int br = (tid & 255) >> 3, bq = (tid & 7) * 16;
    int bsub = bq >> 6, bcol = bq & 63;
    int wid = tid >> 5, lane = tid & 31;
    int wg = wid >> 3, wl = wid & 7;
    int wm = (wl & 3) * 16, wn = (wl >> 2) * 16;
    int g = lane >> 2, tg = lane & 3;
    int lrow = (lane & 7) + ((lane >> 3) & 1) * 8;
    int lcol = ((lane >> 4) & 1) * 8;

    float acc[2][4];
#pragma unroll
    for (int i = 0; i < 2; i++)
#pragma unroll
        for (int j = 0; j < 4; j++) acc[i][j] = 0.f;

    auto load_pair = [&](int p, int ds) {
        int off = p >> 2, k0 = (p & 3) * 128;
        int dy = off / 3 - 1, dx = off % 3 - 1;
        bool valid = ((unsigned)(th + dy) < 32u) && ((unsigned)(tw + dx) < 32u);
        const bf16* srcA = X + ((long)(t + dy * 32 + dx)) * DIM + k0 + aq;
        cp16p(&As[ds * 2 + asub][ar][acol],     srcA,     valid);
        cp16p(&As[ds * 2 + asub][ar][acol + 8], srcA + 8, valid);
        if (tid < 256) {
            const bf16* srcB = W + (size_t)(off * MIDC + br) * DIM + k0 + bq;
            cp16(&Bs[ds * 2 + bsub][br][bcol],     srcB);
            cp16(&Bs[ds * 2 + bsub][br][bcol + 8], srcB + 8);
        }
    };

    load_pair(0, 0);
    CP_COMMIT();
    load_pair(1, 1);
    CP_COMMIT();
    for (int p = 0; p < 36; p++) {
        int ds = p % 3;
        if (p + 1 < 36) { CP_WAIT(1); } else { CP_WAIT(0); }
        __syncthreads();
        if (p + 2 < 36) {
            load_pair(p + 2, (p + 2) % 3);
            CP_COMMIT();
        }
        int buf = ds * 2 + wg;
#pragma unroll
        for (int kc = 0; kc < 4; kc++) {
            int kb = kc * 16;
            unsigned a[4], bb[4];
            ldmx4(a,  &As[buf][wm + lrow][kb + lcol]);
            ldmx4(bb, &Bs[buf][wn + lrow][kb + lcol]);
            unsigned b0[2] = { bb[0], bb[2] };
            unsigned b1[2] = { bb[1], bb[3] };
            mma16816(acc[0], a, b0);
            mma16816(acc[1], a, b1);
        }
    }
    if (wg == 1) {
#pragma unroll
        for (int ni = 0; ni < 2; ni++)
#pragma unroll
            for (int rr = 0; rr < 2; rr++)
#pragma unroll
                for (int j = 0; j < 2; j++)
                    pbuf[wl][g + rr * 8][ni * 8 + tg * 2 + j] = acc[ni][rr * 2 + j];
    }
    __syncthreads();
    if (wg == 0) {
#pragma unroll
        for (int ni = 0; ni < 2; ni++)
#pragma unroll
            for (int rr = 0; rr < 2; rr++) {
                int col = wn + ni * 8 + tg * 2;
                int row = wm + g + rr * 8;
                float v0 = acc[ni][rr * 2 + 0] + pbuf[wl][g + rr * 8][ni * 8 + tg * 2 + 0];
                float v1 = acc[ni][rr * 2 + 1] + pbuf[wl][g + rr * 8][ni * 8 + tg * 2 + 1];
                v0 = fmaxf(v0 * sS[col]     + sT[col],     0.f);
                v1 = fmaxf(v1 * sS[col + 1] + sT[col + 1], 0.f);
                __nv_bfloat162 pk;
                pk.x = __float2bfloat16(v0);
                pk.y = __float2bfloat16(v1);
                *(__nv_bfloat162*)&O[(size_t)(m0 + row) * MIDC + col] = pk;
            }
    }
}

// ---------------- conv2: halo-resident, barrier-free mainloop ---------------
#define C2_HS_BYTES (6 * 34 * 40 * 2)
#define C2_BS_BYTES (9 * 64 * 40 * 2)
#define C2_SMEM (C2_HS_BYTES + C2_BS_BYTES + 128)
__global__ __launch_bounds__(256) void conv2_tok(
    const bf16* __restrict__ Hx, const bf16* __restrict__ W,
    const float* __restrict__ b2, const bf16* __restrict__ res,
    bf16* __restrict__ O)
{
    extern __shared__ __align__(16) char dsm2[];
    bf16 (*hs)[34][40] = (bf16(*)[34][40])dsm2;
    bf16 (*bs)[64][40] = (bf16(*)[64][40])(dsm2 + C2_HS_BYTES);
    int n0 = blockIdx.x * 64, m0 = blockIdx.y * 128;
    int b = m0 >> 10;
    int row0 = (m0 >> 5) & 31;
    int tid = threadIdx.x;

    for (int idx = tid; idx < 816; idx += 256) {
        int pos = idx >> 2, chk = idx & 3;
        int r = pos / 34, c = pos - r * 34;
        int trow = row0 + r - 1, tcol = c - 1;
        bool valid = ((unsigned)trow < 32u) && ((unsigned)tcol < 32u);
        const bf16* src = Hx + ((size_t)(b * NPIX + trow * 32 + tcol)) * MIDC + chk * 8;
        cp16p(&hs[r][c][chk * 8], src, valid);
    }
    {
        int row = tid >> 2, chk = tid & 3;
#pragma unroll
        for (int off = 0; off < 9; off++)
            cp16(&bs[off][row][chk * 8],
                 &W[(size_t)(off * DIM + n0 + row) * MIDC + chk * 8]);
    }
    CP_COMMIT();
    CP_WAIT(0);
    __syncthreads();

    int wid = tid >> 5, lane = tid & 31;
    int wm = (wid & 3) * 32, wn = (wid >> 2) * 32;
    int g = lane >> 2, tg = lane & 3;
    int lrow = (lane & 7) + ((lane >> 3) & 1) * 8;
    int lcol = ((lane >> 4) & 1) * 8;

    float acc[2][4][4];
#pragma unroll
    for (int i = 0; i < 2; i++)
#pragma unroll
        for (int j = 0; j < 4; j++)
#pragma unroll
            for (int k = 0; k < 4; k++) acc[i][j][k] = 0.f;

    const bf16* abase[2];
#pragma unroll
    for (int mi = 0; mi < 2; mi++) {
        int tok = wm + mi * 16 + lrow;
        int tr = tok >> 5, tc = tok & 31;
        abase[mi] = &hs[tr + 1][tc + 1][lcol];
    }

#pragma unroll
    for (int off = 0; off < 9; off++) {
        int dy = off / 3 - 1, dx = off % 3 - 1;
        int shift = (dy * 34 + dx) * 40;
#pragma unroll
        for (int kc = 0; kc < 2; kc++) {
            int kb = kc * 16;
            unsigned a[2][4], bb[2][4];
#pragma unroll
            for (int mi = 0; mi < 2; mi++)
                ldmx4(a[mi], abase[mi] + shift + kb);
#pragma unroll
            for (int nh = 0; nh < 2; nh++)
                ldmx4(bb[nh], &bs[off][wn + nh * 16 + lrow][kb + lcol]);
#pragma unroll
            for (int mi = 0; mi < 2; mi++)
#pragma unroll
                for (int ni = 0; ni < 4; ni++) {
                    unsigned bfr[2] = { bb[ni >> 1][ni & 1], bb[ni >> 1][(ni & 1) + 2] };
                    mma16816(acc[mi][ni], a[mi], bfr);
                }
        }
    }
    float bv0[4], bv1[4];
#pragma unroll
    for (int ni = 0; ni < 4; ni++) {
        int col = n0 + wn + ni * 8 + tg * 2;
        bv0[ni] = b2[col];
        bv1[ni] = b2[col + 1];
    }
#pragma unroll
    for (int mi = 0; mi < 2; mi++)
#pragma unroll
        for (int ni = 0; ni < 4; ni++)
#pragma unroll
            for (int rr = 0; rr < 2; rr++) {
                int row = m0 + wm + mi * 16 + g + rr * 8;
                size_t ad = (size_t)row * DIM + n0 + wn + ni * 8 + tg * 2;
                float v0 = acc[mi][ni][rr * 2 + 0] + bv0[ni];
                float v1 = acc[mi][ni][rr * 2 + 1] + bv1[ni];
                if (res) {
                    __nv_bfloat162 rv = *(const __nv_bfloat162*)&res[ad];
                    v0 += __bfloat162float(rv.x);
                    v1 += __bfloat162float(rv.y);
                }
                __nv_bfloat162 p;
                p.x = __float2bfloat16(v0);
                p.y = __float2bfloat16(v1);
                *(__nv_bfloat162*)&O[ad] = p;
            }
}

// ---------------- circ: reads tokens, computes means, writes bf16 y ---------
__global__ __launch_bounds__(256) void circ_tok(
    const bf16* __restrict__ Xt, const bf16* __restrict__ KWt,
    const float* __restrict__ bias, bf16* __restrict__ y)
{
    __shared__ float xs[4][32][36];
    __shared__ float ks[4][32][36];
    __shared__ float kv[4][32];
    int p0 = blockIdx.x * 4;
    int b = p0 >> 9;
    int c0 = p0 & 511;
    int tid = threadIdx.x;
    int lp = tid >> 6, lt = tid & 63;
    int c = c0 + lp;

#pragma unroll
    for (int i = 0; i < 4; i++) {
        int tok = tid + i * 256;
        int hh = tok >> 5, ww = tok & 31;
        size_t base = (size_t)(b * NPIX + tok) * DIM + c0;
        uint2 xv = *(const uint2*)&Xt[base];
        uint2 kw = *(const uint2*)&KWt[base];
        const __nv_bfloat162* xh = (const __nv_bfloat162*)&xv;
        const __nv_bfloat162* kh = (const __nv_bfloat162*)&kw;
        xs[0][hh][ww] = __bfloat162float(xh[0].x);
        xs[1][hh][ww] = __bfloat162float(xh[0].y);
        xs[2][hh][ww] = __bfloat162float(xh[1].x);
        xs[3][hh][ww] = __bfloat162float(xh[1].y);
        ks[0][hh][ww] = __bfloat162float(kh[0].x);
        ks[1][hh][ww] = __bfloat162float(kh[0].y);
        ks[2][hh][ww] = __bfloat162float(kh[1].x);
        ks[3][hh][ww] = __bfloat162float(kh[1].y);
    }
    __syncthreads();
    if (lt < 32) {
        float s = 0.f;
        if (c < 256) {
#pragma unroll
            for (int ww = 0; ww < 32; ww++) s += ks[lp][lt][ww];
        } else {
#pragma unroll
            for (int hh = 0; hh < 32; hh++) s += ks[lp][hh][lt];
        }
        kv[lp][lt] = s * (1.f / 32.f);
    }
    __syncthreads();

    int t_r = (lt >> 3) * 4;
    int t_c = (lt & 7) * 4;
    float acc[4][4];
#pragma unroll
    for (int r = 0; r < 4; r++)
#pragma unroll
        for (int cc2 = 0; cc2 < 4; cc2++) acc[r][cc2] = 0.f;
    float bv = bias[c];

    if (c < 256) {
        float kr[32];
#pragma unroll
        for (int u = 0; u < 32; u++) kr[u] = kv[lp][(u - t_r) & 31];
#pragma unroll
        for (int j = 0; j < 32; j++) {
            float4 xv = *(const float4*)&xs[lp][j][t_c];
#pragma unroll
            for (int ri = 0; ri < 4; ri++) {
                float kk = kr[(j - ri) & 31];
                acc[ri][0] += kk * xv.x;
                acc[ri][1] += kk * xv.y;
                acc[ri][2] += kk * xv.z;
                acc[ri][3] += kk * xv.w;
            }
        }
    } else {
        float kr[32];
#pragma unroll
        for (int u = 0; u < 32; u++) kr[u] = kv[lp][(u - t_c) & 31];
#pragma unroll
        for (int j = 0; j < 32; j++) {
            float xv[4];
#pragma unroll
            for (int ri = 0; ri < 4; ri++) xv[ri] = xs[lp][t_r + ri][j];
#pragma unroll
            for (int ci = 0; ci < 4; ci++) {
                float kk = kr[(j - ci) & 31];
#pragma unroll
                for (int ri = 0; ri < 4; ri++) acc[ri][ci] += kk * xv[ri];
            }
        }
    }
    bf16* yp = y + (size_t)(p0 + lp) * NPIX;
#pragma unroll
    for (int ri = 0; ri < 4; ri++) {
        union { uint2 q; bf16 h[4]; } pk;
        pk.h[0] = __float2bfloat16(acc[ri][0] + bv);
        pk.h[1] = __float2bfloat16(acc[ri][1] + bv);
        pk.h[2] = __float2bfloat16(acc[ri][2] + bv);
        pk.h[3] = __float2bfloat16(acc[ri][3] + bv);
        *(uint2*)&yp[(t_r + ri) * 32 + t_c] = pk.q;
    }
}

// ---------------- LayerNorm: bf16 NCHW in, bf16 tokens out ------------------
__global__ __launch_bounds__(256) void ln2_kernel(
    const bf16* __restrict__ Y, const float* __restrict__ lnw,
    const float* __restrict__ lnb, bf16* __restrict__ O)
{
    __shared__ float red[256], red2[256];
    __shared__ float mus[64], rss[64];
    int chunk = blockIdx.x, b = blockIdx.y;
    int hw0 = chunk * 64;
    int tid = threadIdx.x;
    int j = tid & 63, q = tid >> 6;
    const bf16* yb = Y + (size_t)b * DIM * NPIX + hw0 + j;
    float s = 0.f, s2 = 0.f;
    for (int c = q * 128; c < q * 128 + 128; c++) {
        float v = __bfloat162float(yb[(size_t)c * NPIX]);
        s += v; s2 += v * v;
    }
    red[tid] = s; red2[tid] = s2;
    __syncthreads();
    if (tid < 64) {
        float S = red[tid] + red[tid + 64] + red[tid + 128] + red[tid + 192];
        float S2 = red2[tid] + red2[tid + 64] + red2[tid + 128] + red2[tid + 192];
        float mu = S * (1.f / 512.f);
        float var = S2 * (1.f / 512.f) - mu * mu;
        mus[tid] = mu;
        rss[tid] = rsqrtf(var + 1e-6f);
    }
    __syncthreads();
    float mu = mus[j], rstd = rss[j];
    size_t t0 = (size_t)b * NPIX + hw0;
    for (int c8 = q * 128; c8 < q * 128 + 128; c8 += 8) {
        union { uint4 u; bf16 h[8]; } pk;
#pragma unroll
        for (int i = 0; i < 8; i++) {
            int c = c8 + i;
            float v = __bfloat162float(yb[(size_t)c * NPIX]);
            pk.h[i] = __float2bfloat16((v - mu) * rstd * __ldg(&lnw[c]) + __ldg(&lnb[c]));
        }
        *(uint4*)&O[(t0 + j) * DIM + c8] = pk.u;
    }
}

__device__ __forceinline__ float gelu_exact(float x) {
    return 0.5f * x * (1.f + erff(x * 0.70710678118654752f));
}

// -------- MLP GEMMs: BM=256, BN=128, BK=32, 512 threads, 4-stage pipeline ---
#define GBM 256
#define GBN 128
#define SSTR 40
#define G_AS_BYTES (4 * GBM * SSTR * 2)     // 81920
#define G_BS_BYTES (4 * GBN * SSTR * 2)     // 40960
#define G_SMEM (G_AS_BYTES + G_BS_BYTES)    // 122880

// GEMM1: C[16384,2048] = gelu(A[16384,512] * W1[2048,512]^T + b)
__global__ __launch_bounds__(512) void gemm1_gelu(
    const bf16* __restrict__ A, const bf16* __restrict__ Bw,
    const float* __restrict__ bias, bf16* __restrict__ C)
{
    const int K = DIM, KT = K / 32;
    extern __shared__ __align__(16) char dsg1[];
    bf16 (*As)[GBM][SSTR] = (bf16(*)[GBM][SSTR])dsg1;
    bf16 (*Bs)[GBN][SSTR] = (bf16(*)[GBN][SSTR])(dsg1 + G_AS_BYTES);
    int m0 = blockIdx.y * GBM, n0 = blockIdx.x * GBN;
    int tid = threadIdx.x;
    int wid = tid >> 5, lane = tid & 31;
    int wm = (wid & 3) * 64, wn = (wid >> 2) * 32;
    int g = lane >> 2, tg = lane & 3;
    int lrow = (lane & 7) + ((lane >> 3) & 1) * 8;
    int lcol = ((lane >> 4) & 1) * 8;
    float acc[4][4][4];
#pragma unroll
    for (int i = 0; i < 4; i++)
#pragma unroll
        for (int j = 0; j < 4; j++)
#pragma unroll
            for (int k = 0; k < 4; k++) acc[i][j][k] = 0.f;

    int lr = tid >> 1, lc = (tid & 1) * 16;
    const bf16* apb = &A[(size_t)(m0 + lr) * K + lc];
    const bf16* bpb = &Bw[(size_t)(n0 + lr) * K + lc];

    auto load_tile = [&](int kt, int buf) {
        cp16(&As[buf][lr][lc],     apb + kt * 32);
        cp16(&As[buf][lr][lc + 8], apb + kt * 32 + 8);
        if (tid < 256) {
            cp16(&Bs[buf][lr][lc],     bpb + kt * 32);
            cp16(&Bs[buf][lr][lc + 8], bpb + kt * 32 + 8);
        }
    };

    load_tile(0, 0);
    CP_COMMIT();
    load_tile(1, 1);
    CP_COMMIT();
    load_tile(2, 2);
    CP_COMMIT();
    for (int kt = 0; kt < KT; kt++) {
        int buf = kt & 3;
        if (kt + 2 < KT)      { CP_WAIT(2); }
        else if (kt + 1 < KT) { CP_WAIT(1); }
        else                  { CP_WAIT(0); }
        __syncthreads();
        if (kt + 3 < KT) {
            load_tile(kt + 3, (kt + 3) & 3);
            CP_COMMIT();
        }
#pragma unroll
        for (int ks = 0; ks < 2; ks++) {
            int kb = ks * 16;
            unsigned af[4][4], bb[2][4];
#pragma unroll
            for (int mi = 0; mi < 4; mi++)
                ldmx4(af[mi], &As[buf][wm + mi * 16 + lrow][kb + lcol]);
#pragma unroll
            for (int nh = 0; nh < 2; nh++)
                ldmx4(bb[nh], &Bs[buf][wn + nh * 16 + lrow][kb + lcol]);
#pragma unroll
            for (int mi = 0; mi < 4; mi++)
#pragma unroll
                for (int ni = 0; ni < 4; ni++) {
                    unsigned bfr[2] = { bb[ni >> 1][ni & 1], bb[ni >> 1][(ni & 1) + 2] };
                    mma16816(acc[mi][ni], af[mi], bfr);
                }
        }
    }
#pragma unroll
    for (int mi = 0; mi < 4; mi++)
#pragma unroll
        for (int ni = 0; ni < 4; ni++) {
            int col = n0 + wn + ni * 8 + tg * 2;
            float b0 = bias[col], b1 = bias[col + 1];
            int row0 = m0 + wm + mi * 16 + g;
#pragma unroll
            for (int rr = 0; rr < 2; rr++) {
                int r = row0 + rr * 8;
                float v0 = gelu_exact(acc[mi][ni][rr * 2 + 0] + b0);
                float v1 = gelu_exact(acc[mi][ni][rr * 2 + 1] + b1);
                __nv_bfloat162 p;
                p.x = __float2bfloat16(v0);
                p.y = __float2bfloat16(v1);
                *(__nv_bfloat162*)&C[(size_t)r * FDIM + col] = p;
            }
        }
}

// GEMM2: out = x_in + gamma*(A[16384,2048]*W2[512,2048]^T + b), NCHW epilogue
__global__ __launch_bounds__(512) void gemm2_res(
    const bf16* __restrict__ A, const bf16* __restrict__ Bw,
    const float* __restrict__ bias2, const float* __restrict__ gamma,
    const float* __restrict__ xin, float* __restrict__ out)
{
    const int K = FDIM, KT = K / 32;
    extern __shared__ __align__(16) char dsg2[];
    bf16 (*As)[GBM][SSTR] = (bf16(*)[GBM][SSTR])dsg2;
    bf16 (*Bs)[GBN][SSTR] = (bf16(*)[GBN][SSTR])(dsg2 + G_AS_BYTES);
    int m0 = blockIdx.y * GBM, n0 = blockIdx.x * GBN;
    int tid = threadIdx.x;
    int wid = tid >> 5, lane = tid & 31;
    int wm = (wid & 3) * 64, wn = (wid >> 2) * 32;
    int g = lane >> 2, tg = lane & 3;
    int lrow = (lane & 7) + ((lane >> 3) & 1) * 8;
    int lcol = ((lane >> 4) & 1) * 8;
    float acc[4][4][4];
#pragma unroll
    for (int i = 0; i < 4; i++)
#pragma unroll
        for (int j = 0; j < 4; j++)
#pragma unroll
            for (int k = 0; k < 4; k++) acc[i][j][k] = 0.f;

    int lr = tid >> 1, lc = (tid & 1) * 16;
    const bf16* apb = &A[(size_t)(m0 + lr) * K + lc];
    const bf16* bpb = &Bw[(size_t)(n0 + lr) * K + lc];

    auto load_tile = [&](int kt, int buf) {
        cp16(&As[buf][lr][lc],     apb + kt * 32);
        cp16(&As[buf][lr][lc + 8], apb + kt * 32 + 8);
        if (tid < 256) {
            cp16(&Bs[buf][lr][lc],     bpb + kt * 32);
            cp16(&Bs[buf][lr][lc + 8], bpb + kt * 32 + 8);
        }
    };

    load_tile(0, 0);
    CP_COMMIT();
    load_tile(1, 1);
    CP_COMMIT();
    load_tile(2, 2);
    CP_COMMIT();
    for (int kt = 0; kt < KT; kt++) {
        int buf = kt & 3;
        if (kt + 2 < KT)      { CP_WAIT(2); }
        else if (kt + 1 < KT) { CP_WAIT(1); }
        else                  { CP_WAIT(0); }
        __syncthreads();
        if (kt + 3 < KT) {
            load_tile(kt + 3, (kt + 3) & 3);
            CP_COMMIT();
        }
#pragma unroll
        for (int ks = 0; ks < 2; ks++) {
            int kb = ks * 16;
            unsigned af[4][4], bb[2][4];
#pragma unroll
            for (int mi = 0; mi < 4; mi++)
                ldmx4(af[mi], &As[buf][wm + mi * 16 + lrow][kb + lcol]);
#pragma unroll
            for (int nh = 0; nh < 2; nh++)
                ldmx4(bb[nh], &Bs[buf][wn + nh * 16 + lrow][kb + lcol]);
#pragma unroll
            for (int mi = 0; mi < 4; mi++)
#pragma unroll
                for (int ni = 0; ni < 4; ni++) {
                    unsigned bfr[2] = { bb[ni >> 1][ni & 1], bb[ni >> 1][(ni & 1) + 2] };
                    mma16816(acc[mi][ni], af[mi], bfr);
                }
        }
    }
    __syncthreads();
    // epilogue: 32-col chunks through smem (256 rows) -> coalesced NCHW writes
    float (*sbuf)[33] = (float(*)[33])dsg2;
    int cc = tid >> 4, seg = tid & 15;
#pragma unroll
    for (int nc = 0; nc < 4; nc++) {
        if ((wid >> 2) == nc) {
#pragma unroll
            for (int mi = 0; mi < 4; mi++)
#pragma unroll
                for (int ni = 0; ni < 4; ni++)
#pragma unroll
                    for (int rr = 0; rr < 2; rr++)
#pragma unroll
                        for (int j = 0; j < 2; j++)
                            sbuf[wm + mi * 16 + g + rr * 8][ni * 8 + tg * 2 + j] =
                                acc[mi][ni][rr * 2 + j];
        }
        __syncthreads();
        int col = n0 + nc * 32 + cc;
        float gb = gamma[col], bb2 = bias2[col];
        size_t colbase = ((size_t)(m0 >> 10) * DIM + col) * NPIX + (m0 & 1023);
#pragma unroll
        for (int q = 0; q < 4; q++) {
            int r = q * 64 + seg * 4;
            float4 xv = *(const float4*)&xin[colbase + r];
            float4 o;
            o.x = xv.x + gb * (sbuf[r + 0][cc] + bb2);
            o.y = xv.y + gb * (sbuf[r + 1][cc] + bb2);
            o.z = xv.z + gb * (sbuf[r + 2][cc] + bb2);
            o.w = xv.w + gb * (sbuf[r + 3][cc] + bb2);
            *(float4*)&out[colbase + r] = o;
        }
        __syncthreads();
    }
}

// ---------------- host launcher ----------------
extern "C" void kernel_launch(void* const* d_in, const int* in_sizes, int n_in,
                              void* d_out, int out_size)
{
    const float* x      = (const float*)d_in[0];
    const float* pe_w1  = (const float*)d_in[1];
    const float* pe_bng = (const float*)d_in[2];
    const float* pe_bnb = (const float*)d_in[3];
    const float* pe_bnm = (const float*)d_in[4];
    const float* pe_bnv = (const float*)d_in[5];
    const float* pe_w2  = (const float*)d_in[6];
    const float* pe_b2  = (const float*)d_in[7];
    const float* kg_w1  = (const float*)d_in[8];
    const float* kg_bng = (const float*)d_in[9];
    const float* kg_bnb = (const float*)d_in[10];
    const float* kg_bnm = (const float*)d_in[11];
    const float* kg_bnv = (const float*)d_in[12];
    const float* kg_w2  = (const float*)d_in[13];
    const float* kg_b2  = (const float*)d_in[14];
    const float* bias   = (const float*)d_in[15];
    const float* ln_w   = (const float*)d_in[16];
    const float* ln_b   = (const float*)d_in[17];
    const float* pw1_w  = (const float*)d_in[18];
    const float* pw1_b  = (const float*)d_in[19];
    const float* pw2_w  = (const float*)d_in[20];
    const float* pw2_b  = (const float*)d_in[21];
    const float* gamma  = (const float*)d_in[22];
    float* outp = (float*)d_out;

    bf16 *pxtok, *pxtok2, *phtok, *pkwtok, *pybf, *pmid, *pw1bf, *pw2bf;
    bf16 *pw1pe, *pw1kg, *pw2pe, *pw2kg, *py;
    cudaGetSymbolAddress((void**)&pxtok,  g_xtok);
    cudaGetSymbolAddress((void**)&pxtok2, g_xtok2);
    cudaGetSymbolAddress((void**)&phtok,  g_htok);
    cudaGetSymbolAddress((void**)&pkwtok, g_kwtok);
    cudaGetSymbolAddress((void**)&py,  g_y);
    cudaGetSymbolAddress((void**)&pybf,  g_ybf);
    cudaGetSymbolAddress((void**)&pmid,  g_mid);
    cudaGetSymbolAddress((void**)&pw1bf, g_w1bf);
    cudaGetSymbolAddress((void**)&pw2bf, g_w2bf);
    cudaGetSymbolAddress((void**)&pw1pe, g_w1pe);
    cudaGetSymbolAddress((void**)&pw1kg, g_w1kg);
    cudaGetSymbolAddress((void**)&pw2pe, g_w2pe);
    cudaGetSymbolAddress((void**)&pw2kg, g_w2kg);

    cudaFuncSetAttribute(conv1_tok, cudaFuncAttributeMaxDynamicSharedMemorySize, C1_SMEM);
    cudaFuncSetAttribute(conv2_tok, cudaFuncAttributeMaxDynamicSharedMemorySize, C2_SMEM);
    cudaFuncSetAttribute(gemm1_gelu, cudaFuncAttributeMaxDynamicSharedMemorySize, G_SMEM);
    cudaFuncSetAttribute(gemm2_res, cudaFuncAttributeMaxDynamicSharedMemorySize, G_SMEM);

    cvt_all<<<(FDIM * DIM + 255) / 256, 256>>>(pw1_w, pw2_w, pe_w1, kg_w1, pe_w2, kg_w2,
                                               pw1bf, pw2bf, pw1pe, pw1kg, pw2pe, pw2kg);
    nchw2tok<<<dim3(8, 4, BATCH), 256>>>(x, pxtok);

    conv1_tok<<<NTOK / 64, 512, C1_SMEM>>>(pxtok, pw1pe, pe_bng, pe_bnb, pe_bnm, pe_bnv, phtok);
    conv2_tok<<<dim3(8, NTOK / 128), 256, C2_SMEM>>>(phtok, pw2pe, pe_b2, pxtok, pxtok2);
    conv1_tok<<<NTOK / 64, 512, C1_SMEM>>>(pxtok2, pw1kg, kg_bng, kg_bnb, kg_bnm, kg_bnv, phtok);
    conv2_tok<<<dim3(8, NTOK / 128), 256, C2_SMEM>>>(phtok, pw2kg, kg_b2, nullptr, pkwtok);

    circ_tok<<<(BATCH * DIM) / 4, 256>>>(pxtok2, pkwtok, bias, py);

    ln2_kernel<<<dim3(16, BATCH), 256>>>(py, ln_w, ln_b, pybf);

    gemm1_gelu<<<dim3(FDIM / GBN, NTOK / GBM), 512, G_SMEM>>>(pybf, pw1bf, pw1_b, pmid);
    gemm2_res<<<dim3(DIM / GBN, NTOK / GBM), 512, G_SMEM>>>(pmid, pw2bf, pw2_b, gamma, x, outp);
}

// round 16
// speedup vs baseline: 1.1537x; 1.0886x over previous
#include <cuda_runtime.h>
#include <cuda_bf16.h>
#include <cuda_fp8.h>
#include <math.h>

#define BATCH 16
#define DIM 512
#define MIDC 32
#define NPIX 1024
#define NTOK 16384
#define FDIM 2048

typedef __nv_bfloat16 bf16;
typedef __nv_fp8_storage_t f8;

// ---------------- scratch (static device memory) ----------------
__device__ bf16 g_xtok [NTOK * DIM];
__device__ bf16 g_xtok2[NTOK * DIM];
__device__ bf16 g_htok [NTOK * MIDC];
__device__ bf16 g_kwtok[NTOK * DIM];
__device__ bf16 g_y [BATCH * DIM * NPIX];
__device__ f8   g_ybf8[NTOK * DIM];
__device__ f8   g_mid8[NTOK * FDIM];
__device__ f8   g_w1f8[FDIM * DIM];
__device__ f8   g_w2f8[DIM * FDIM];
__device__ bf16 g_w1pe[9 * MIDC * DIM];
__device__ bf16 g_w1kg[9 * MIDC * DIM];
__device__ bf16 g_w2pe[9 * DIM * MIDC];
__device__ bf16 g_w2kg[9 * DIM * MIDC];

// ---------------- cp.async / ldmatrix helpers ----------------
__device__ __forceinline__ void cp16(void* s, const void* g) {
    unsigned sa = (unsigned)__cvta_generic_to_shared(s);
    asm volatile("cp.async.cg.shared.global [%0], [%1], 16;\n" :: "r"(sa), "l"(g));
}
__device__ __forceinline__ void cp16p(void* s, const void* g, bool pred) {
    unsigned sa = (unsigned)__cvta_generic_to_shared(s);
    int sz = pred ? 16 : 0;
    asm volatile("cp.async.cg.shared.global [%0], [%1], 16, %2;\n" :: "r"(sa), "l"(g), "r"(sz));
}
#define CP_COMMIT() asm volatile("cp.async.commit_group;\n")
#define CP_WAIT(n)  asm volatile("cp.async.wait_group %0;\n" :: "n"(n))

__device__ __forceinline__ void ldmx4(unsigned* r, const void* p) {
    unsigned a = (unsigned)__cvta_generic_to_shared(p);
    asm volatile("ldmatrix.sync.aligned.m8n8.x4.shared.b16 {%0,%1,%2,%3}, [%4];\n"
                 : "=r"(r[0]), "=r"(r[1]), "=r"(r[2]), "=r"(r[3]) : "r"(a));
}

// ---------------- merged weight conversion ----------------
__global__ void cvt_all(const float* __restrict__ w1, const float* __restrict__ w2,
                        const float* __restrict__ pw1, const float* __restrict__ kw1,
                        const float* __restrict__ pw2, const float* __restrict__ kw2,
                        f8* __restrict__ o1, f8* __restrict__ o2,
                        bf16* __restrict__ o1p, bf16* __restrict__ o1k,
                        bf16* __restrict__ o2p, bf16* __restrict__ o2k)
{
    int i = blockIdx.x * blockDim.x + threadIdx.x;
    if (i < FDIM * DIM) {
        o1[i] = __nv_cvt_float_to_fp8(w1[i], __NV_SATFINITE, __NV_E4M3);
        o2[i] = __nv_cvt_float_to_fp8(w2[i], __NV_SATFINITE, __NV_E4M3);
    }
    if (i < MIDC * DIM * 9) {
        int off = i % 9;
        int ic = (i / 9) % DIM, oc = i / (9 * DIM);
        o1p[(off * MIDC + oc) * DIM + ic] = __float2bfloat16(pw1[i]);
        o1k[(off * MIDC + oc) * DIM + ic] = __float2bfloat16(kw1[i]);
        int ic2 = (i / 9) % MIDC, oc2 = i / (9 * MIDC);
        o2p[(off * DIM + oc2) * MIDC + ic2] = __float2bfloat16(pw2[i]);
        o2k[(off * DIM + oc2) * MIDC + ic2] = __float2bfloat16(kw2[i]);
    }
}

// ---------------- NCHW fp32 -> token bf16 transpose ----------------
__global__ __launch_bounds__(256) void nchw2tok(const float* __restrict__ X, bf16* __restrict__ T)
{
    __shared__ bf16 sm[128][136];
    int hw0 = blockIdx.x * 128, c0 = blockIdx.y * 128, b = blockIdx.z;
    int tid = threadIdx.x;
    const float* xp = X + ((size_t)b * DIM + c0) * NPIX + hw0;
#pragma unroll
    for (int i = 0; i < 16; i++) {
        int idx = tid + i * 256;
        int rc = idx >> 5, u = idx & 31;
        float4 v = *(const float4*)&xp[(size_t)rc * NPIX + u * 4];
        union { uint2 q; bf16 h[4]; } pk;
        pk.h[0] = __float2bfloat16(v.x); pk.h[1] = __float2bfloat16(v.y);
        pk.h[2] = __float2bfloat16(v.z); pk.h[3] = __float2bfloat16(v.w);
        *(uint2*)&sm[rc][u * 4] = pk.q;
    }
    __syncthreads();
    bf16* tp = T + ((size_t)(b * NPIX + hw0)) * DIM + c0;
#pragma unroll
    for (int i = 0; i < 8; i++) {
        int idx = tid + i * 256;
        int rt = idx >> 4, uu = idx & 15;
        union { uint4 q; bf16 h[8]; } pk;
#pragma unroll
        for (int j = 0; j < 8; j++) pk.h[j] = sm[uu * 8 + j][rt];
        *(uint4*)&tp[(size_t)rt * DIM + uu * 8] = pk.q;
    }
}

// ---------------- MMA helpers ----------------
__device__ __forceinline__ void mma16816(float* d, const unsigned* a, const unsigned* b) {
    asm volatile(
        "mma.sync.aligned.m16n8k16.row.col.f32.bf16.bf16.f32 "
        "{%0,%1,%2,%3}, {%4,%5,%6,%7}, {%8,%9}, {%0,%1,%2,%3};\n"
        : "+f"(d[0]), "+f"(d[1]), "+f"(d[2]), "+f"(d[3])
        : "r"(a[0]), "r"(a[1]), "r"(a[2]), "r"(a[3]), "r"(b[0]), "r"(b[1]));
}
__device__ __forceinline__ void mma16832f8(float* d, const unsigned* a, const unsigned* b) {
    asm volatile(
        "mma.sync.aligned.m16n8k32.row.col.f32.e4m3.e4m3.f32 "
        "{%0,%1,%2,%3}, {%4,%5,%6,%7}, {%8,%9}, {%0,%1,%2,%3};\n"
        : "+f"(d[0]), "+f"(d[1]), "+f"(d[2]), "+f"(d[3])
        : "r"(a[0]), "r"(a[1]), "r"(a[2]), "r"(a[3]), "r"(b[0]), "r"(b[1]));
}

// ---------------- conv1: 512-thread dual-warpgroup K-split -----------------
#define C1S 72
#define C1_AS_BYTES (6 * 64 * C1S * 2)
#define C1_BS_BYTES (6 * 32 * C1S * 2)
#define C1_PB_BYTES (8 * 16 * 16 * 4)
#define C1_SMEM (C1_AS_BYTES + C1_BS_BYTES + C1_PB_BYTES + 256)
__global__ __launch_bounds__(512) void conv1_tok(
    const bf16* __restrict__ X, const bf16* __restrict__ W,
    const float* __restrict__ bng, const float* __restrict__ bnb,
    const float* __restrict__ bnm, const float* __restrict__ bnv,
    bf16* __restrict__ O)
{
    extern __shared__ __align__(16) char dsm[];
    bf16 (*As)[64][C1S] = (bf16(*)[64][C1S])dsm;
    bf16 (*Bs)[32][C1S] = (bf16(*)[32][C1S])(dsm + C1_AS_BYTES);
    float (*pbuf)[16][16] = (float(*)[16][16])(dsm + C1_AS_BYTES + C1_BS_BYTES);
    float* sS = (float*)(dsm + C1_AS_BYTES + C1_BS_BYTES + C1_PB_BYTES);
    float* sT = sS + 32;

    int m0 = blockIdx.x * 64;
    int tid = threadIdx.x;
    if (tid < 32) {
        float inv = rsqrtf(bnv[tid] + 1e-5f);
        float s = bng[tid] * inv;
        sS[tid] = s;
        sT[tid] = bnb[tid] - bnm[tid] * s;
    }
    int ar = tid >> 3, aq = (tid & 7) * 16;
    int asub = aq >> 6, acol = aq & 63;
    int t = m0 + ar;
    int th = (t >> 5) & 31, tw = t & 31;
    int br = (tid & 255) >> 3, bq = (tid & 7) * 16;
    int bsub = bq >> 6, bcol = bq & 63;
    int wid = tid >> 5, lane = tid & 31;
    int wg = wid >> 3, wl = wid & 7;
    int wm = (wl & 3) * 16, wn = (wl >> 2) * 16;
    int g = lane >> 2, tg = lane & 3;
    int lrow = (lane & 7) + ((lane >> 3) & 1) * 8;
    int lcol = ((lane >> 4) & 1) * 8;

    float acc[2][4];
#pragma unroll
    for (int i = 0; i < 2; i++)
#pragma unroll
        for (int j = 0; j < 4; j++) acc[i][j] = 0.f;

    auto load_pair = [&](int p, int ds) {
        int off = p >> 2, k0 = (p & 3) * 128;
        int dy = off / 3 - 1, dx = off % 3 - 1;
        bool valid = ((unsigned)(th + dy) < 32u) && ((unsigned)(tw + dx) < 32u);
        const bf16* srcA = X + ((long)(t + dy * 32 + dx)) * DIM + k0 + aq;
        cp16p(&As[ds * 2 + asub][ar][acol],     srcA,     valid);
        cp16p(&As[ds * 2 + asub][ar][acol + 8], srcA + 8, valid);
        if (tid < 256) {
            const bf16* srcB = W + (size_t)(off * MIDC + br) * DIM + k0 + bq;
            cp16(&Bs[ds * 2 + bsub][br][bcol],     srcB);
            cp16(&Bs[ds * 2 + bsub][br][bcol + 8], srcB + 8);
        }
    };

    load_pair(0, 0);
    CP_COMMIT();
    load_pair(1, 1);
    CP_COMMIT();
    for (int p = 0; p < 36; p++) {
        int ds = p % 3;
        if (p + 1 < 36) { CP_WAIT(1); } else { CP_WAIT(0); }
        __syncthreads();
        if (p + 2 < 36) {
            load_pair(p + 2, (p + 2) % 3);
            CP_COMMIT();
        }
        int buf = ds * 2 + wg;
#pragma unroll
        for (int kc = 0; kc < 4; kc++) {
            int kb = kc * 16;
            unsigned a[4], bb[4];
            ldmx4(a,  &As[buf][wm + lrow][kb + lcol]);
            ldmx4(bb, &Bs[buf][wn + lrow][kb + lcol]);
            unsigned b0[2] = { bb[0], bb[2] };
            unsigned b1[2] = { bb[1], bb[3] };
            mma16816(acc[0], a, b0);
            mma16816(acc[1], a, b1);
        }
    }
    if (wg == 1) {
#pragma unroll
        for (int ni = 0; ni < 2; ni++)
#pragma unroll
            for (int rr = 0; rr < 2; rr++)
#pragma unroll
                for (int j = 0; j < 2; j++)
                    pbuf[wl][g + rr * 8][ni * 8 + tg * 2 + j] = acc[ni][rr * 2 + j];
    }
    __syncthreads();
    if (wg == 0) {
#pragma unroll
        for (int ni = 0; ni < 2; ni++)
#pragma unroll
            for (int rr = 0; rr < 2; rr++) {
                int col = wn + ni * 8 + tg * 2;
                int row = wm + g + rr * 8;
                float v0 = acc[ni][rr * 2 + 0] + pbuf[wl][g + rr * 8][ni * 8 + tg * 2 + 0];
                float v1 = acc[ni][rr * 2 + 1] + pbuf[wl][g + rr * 8][ni * 8 + tg * 2 + 1];
                v0 = fmaxf(v0 * sS[col]     + sT[col],     0.f);
                v1 = fmaxf(v1 * sS[col + 1] + sT[col + 1], 0.f);
                __nv_bfloat162 pk;
                pk.x = __float2bfloat16(v0);
                pk.y = __float2bfloat16(v1);
                *(__nv_bfloat162*)&O[(size_t)(m0 + row) * MIDC + col] = pk;
            }
    }
}

// ---------------- conv2: halo-resident, barrier-free mainloop ---------------
#define C2_HS_BYTES (6 * 34 * 40 * 2)
#define C2_BS_BYTES (9 * 64 * 40 * 2)
#define C2_SMEM (C2_HS_BYTES + C2_BS_BYTES + 128)
__global__ __launch_bounds__(256) void conv2_tok(
    const bf16* __restrict__ Hx, const bf16* __restrict__ W,
    const float* __restrict__ b2, const bf16* __restrict__ res,
    bf16* __restrict__ O)
{
    extern __shared__ __align__(16) char dsm2[];
    bf16 (*hs)[34][40] = (bf16(*)[34][40])dsm2;
    bf16 (*bs)[64][40] = (bf16(*)[64][40])(dsm2 + C2_HS_BYTES);
    int n0 = blockIdx.x * 64, m0 = blockIdx.y * 128;
    int b = m0 >> 10;
    int row0 = (m0 >> 5) & 31;
    int tid = threadIdx.x;

    for (int idx = tid; idx < 816; idx += 256) {
        int pos = idx >> 2, chk = idx & 3;
        int r = pos / 34, c = pos - r * 34;
        int trow = row0 + r - 1, tcol = c - 1;
        bool valid = ((unsigned)trow < 32u) && ((unsigned)tcol < 32u);
        const bf16* src = Hx + ((size_t)(b * NPIX + trow * 32 + tcol)) * MIDC + chk * 8;
        cp16p(&hs[r][c][chk * 8], src, valid);
    }
    {
        int row = tid >> 2, chk = tid & 3;
#pragma unroll
        for (int off = 0; off < 9; off++)
            cp16(&bs[off][row][chk * 8],
                 &W[(size_t)(off * DIM + n0 + row) * MIDC + chk * 8]);
    }
    CP_COMMIT();
    CP_WAIT(0);
    __syncthreads();

    int wid = tid >> 5, lane = tid & 31;
    int wm = (wid & 3) * 32, wn = (wid >> 2) * 32;
    int g = lane >> 2, tg = lane & 3;
    int lrow = (lane & 7) + ((lane >> 3) & 1) * 8;
    int lcol = ((lane >> 4) & 1) * 8;

    float acc[2][4][4];
#pragma unroll
    for (int i = 0; i < 2; i++)
#pragma unroll
        for (int j = 0; j < 4; j++)
#pragma unroll
            for (int k = 0; k < 4; k++) acc[i][j][k] = 0.f;

    const bf16* abase[2];
#pragma unroll
    for (int mi = 0; mi < 2; mi++) {
        int tok = wm + mi * 16 + lrow;
        int tr = tok >> 5, tc = tok & 31;
        abase[mi] = &hs[tr + 1][tc + 1][lcol];
    }

#pragma unroll
    for (int off = 0; off < 9; off++) {
        int dy = off / 3 - 1, dx = off % 3 - 1;
        int shift = (dy * 34 + dx) * 40;
#pragma unroll
        for (int kc = 0; kc < 2; kc++) {
            int kb = kc * 16;
            unsigned a[2][4], bb[2][4];
#pragma unroll
            for (int mi = 0; mi < 2; mi++)
                ldmx4(a[mi], abase[mi] + shift + kb);
#pragma unroll
            for (int nh = 0; nh < 2; nh++)
                ldmx4(bb[nh], &bs[off][wn + nh * 16 + lrow][kb + lcol]);
#pragma unroll
            for (int mi = 0; mi < 2; mi++)
#pragma unroll
                for (int ni = 0; ni < 4; ni++) {
                    unsigned bfr[2] = { bb[ni >> 1][ni & 1], bb[ni >> 1][(ni & 1) + 2] };
                    mma16816(acc[mi][ni], a[mi], bfr);
                }
        }
    }
    float bv0[4], bv1[4];
#pragma unroll
    for (int ni = 0; ni < 4; ni++) {
        int col = n0 + wn + ni * 8 + tg * 2;
        bv0[ni] = b2[col];
        bv1[ni] = b2[col + 1];
    }
#pragma unroll
    for (int mi = 0; mi < 2; mi++)
#pragma unroll
        for (int ni = 0; ni < 4; ni++)
#pragma unroll
            for (int rr = 0; rr < 2; rr++) {
                int row = m0 + wm + mi * 16 + g + rr * 8;
                size_t ad = (size_t)row * DIM + n0 + wn + ni * 8 + tg * 2;
                float v0 = acc[mi][ni][rr * 2 + 0] + bv0[ni];
                float v1 = acc[mi][ni][rr * 2 + 1] + bv1[ni];
                if (res) {
                    __nv_bfloat162 rv = *(const __nv_bfloat162*)&res[ad];
                    v0 += __bfloat162float(rv.x);
                    v1 += __bfloat162float(rv.y);
                }
                __nv_bfloat162 p;
                p.x = __float2bfloat16(v0);
                p.y = __float2bfloat16(v1);
                *(__nv_bfloat162*)&O[ad] = p;
            }
}

// ---------------- circ: reads tokens, computes means, writes bf16 y ---------
__global__ __launch_bounds__(256) void circ_tok(
    const bf16* __restrict__ Xt, const bf16* __restrict__ KWt,
    const float* __restrict__ bias, bf16* __restrict__ y)
{
    __shared__ float xs[4][32][36];
    __shared__ float ks[4][32][36];
    __shared__ float kv[4][32];
    int p0 = blockIdx.x * 4;
    int b = p0 >> 9;
    int c0 = p0 & 511;
    int tid = threadIdx.x;
    int lp = tid >> 6, lt = tid & 63;
    int c = c0 + lp;

#pragma unroll
    for (int i = 0; i < 4; i++) {
        int tok = tid + i * 256;
        int hh = tok >> 5, ww = tok & 31;
        size_t base = (size_t)(b * NPIX + tok) * DIM + c0;
        uint2 xv = *(const uint2*)&Xt[base];
        uint2 kw = *(const uint2*)&KWt[base];
        const __nv_bfloat162* xh = (const __nv_bfloat162*)&xv;
        const __nv_bfloat162* kh = (const __nv_bfloat162*)&kw;
        xs[0][hh][ww] = __bfloat162float(xh[0].x);
        xs[1][hh][ww] = __bfloat162float(xh[0].y);
        xs[2][hh][ww] = __bfloat162float(xh[1].x);
        xs[3][hh][ww] = __bfloat162float(xh[1].y);
        ks[0][hh][ww] = __bfloat162float(kh[0].x);
        ks[1][hh][ww] = __bfloat162float(kh[0].y);
        ks[2][hh][ww] = __bfloat162float(kh[1].x);
        ks[3][hh][ww] = __bfloat162float(kh[1].y);
    }
    __syncthreads();
    if (lt < 32) {
        float s = 0.f;
        if (c < 256) {
#pragma unroll
            for (int ww = 0; ww < 32; ww++) s += ks[lp][lt][ww];
        } else {
#pragma unroll
            for (int hh = 0; hh < 32; hh++) s += ks[lp][hh][lt];
        }
        kv[lp][lt] = s * (1.f / 32.f);
    }
    __syncthreads();

    int t_r = (lt >> 3) * 4;
    int t_c = (lt & 7) * 4;
    float acc[4][4];
#pragma unroll
    for (int r = 0; r < 4; r++)
#pragma unroll
        for (int cc2 = 0; cc2 < 4; cc2++) acc[r][cc2] = 0.f;
    float bv = bias[c];

    if (c < 256) {
        float kr[32];
#pragma unroll
        for (int u = 0; u < 32; u++) kr[u] = kv[lp][(u - t_r) & 31];
#pragma unroll
        for (int j = 0; j < 32; j++) {
            float4 xv = *(const float4*)&xs[lp][j][t_c];
#pragma unroll
            for (int ri = 0; ri < 4; ri++) {
                float kk = kr[(j - ri) & 31];
                acc[ri][0] += kk * xv.x;
                acc[ri][1] += kk * xv.y;
                acc[ri][2] += kk * xv.z;
                acc[ri][3] += kk * xv.w;
            }
        }
    } else {
        float kr[32];
#pragma unroll
        for (int u = 0; u < 32; u++) kr[u] = kv[lp][(u - t_c) & 31];
#pragma unroll
        for (int j = 0; j < 32; j++) {
            float xv[4];
#pragma unroll
            for (int ri = 0; ri < 4; ri++) xv[ri] = xs[lp][t_r + ri][j];
#pragma unroll
            for (int ci = 0; ci < 4; ci++) {
                float kk = kr[(j - ci) & 31];
#pragma unroll
                for (int ri = 0; ri < 4; ri++) acc[ri][ci] += kk * xv[ri];
            }
        }
    }
    bf16* yp = y + (size_t)(p0 + lp) * NPIX;
#pragma unroll
    for (int ri = 0; ri < 4; ri++) {
        union { uint2 q; bf16 h[4]; } pk;
        pk.h[0] = __float2bfloat16(acc[ri][0] + bv);
        pk.h[1] = __float2bfloat16(acc[ri][1] + bv);
        pk.h[2] = __float2bfloat16(acc[ri][2] + bv);
        pk.h[3] = __float2bfloat16(acc[ri][3] + bv);
        *(uint2*)&yp[(t_r + ri) * 32 + t_c] = pk.q;
    }
}

// ---------------- LayerNorm: bf16 NCHW in, fp8 tokens out -------------------
__global__ __launch_bounds__(256) void ln2_kernel(
    const bf16* __restrict__ Y, const float* __restrict__ lnw,
    const float* __restrict__ lnb, f8* __restrict__ O)
{
    __shared__ float red[256], red2[256];
    __shared__ float mus[64], rss[64];
    int chunk = blockIdx.x, b = blockIdx.y;
    int hw0 = chunk * 64;
    int tid = threadIdx.x;
    int j = tid & 63, q = tid >> 6;
    const bf16* yb = Y + (size_t)b * DIM * NPIX + hw0 + j;
    float s = 0.f, s2 = 0.f;
    for (int c = q * 128; c < q * 128 + 128; c++) {
        float v = __bfloat162float(yb[(size_t)c * NPIX]);
        s += v; s2 += v * v;
    }
    red[tid] = s; red2[tid] = s2;
    __syncthreads();
    if (tid < 64) {
        float S = red[tid] + red[tid + 64] + red[tid + 128] + red[tid + 192];
        float S2 = red2[tid] + red2[tid + 64] + red2[tid + 128] + red2[tid + 192];
        float mu = S * (1.f / 512.f);
        float var = S2 * (1.f / 512.f) - mu * mu;
        mus[tid] = mu;
        rss[tid] = rsqrtf(var + 1e-6f);
    }
    __syncthreads();
    float mu = mus[j], rstd = rss[j];
    size_t t0 = (size_t)b * NPIX + hw0;
    for (int c8 = q * 128; c8 < q * 128 + 128; c8 += 8) {
        union { uint2 u; f8 h[8]; } pk;
#pragma unroll
        for (int i = 0; i < 8; i++) {
            int c = c8 + i;
            float v = __bfloat162float(yb[(size_t)c * NPIX]);
            float o = (v - mu) * rstd * __ldg(&lnw[c]) + __ldg(&lnb[c]);
            pk.h[i] = __nv_cvt_float_to_fp8(o, __NV_SATFINITE, __NV_E4M3);
        }
        *(uint2*)&O[(t0 + j) * DIM + c8] = pk.u;
    }
}

__device__ __forceinline__ float gelu_exact(float x) {
    return 0.5f * x * (1.f + erff(x * 0.70710678118654752f));
}

// ---- FP8 MLP GEMMs: BM=256, BN=128, BK=64 fp8, 512 threads, 4-stage --------
// smem rows: 64 fp8 (= 32 b16 units) + pad -> SSTR 40 b16 = 80 B/row
#define GBM 256
#define GBN 128
#define SSTR 40
#define G_AS_BYTES (4 * GBM * SSTR * 2)     // 81920
#define G_BS_BYTES (4 * GBN * SSTR * 2)     // 40960
#define G_SMEM (G_AS_BYTES + G_BS_BYTES)    // 122880

// GEMM1: mid8 = fp8(gelu(A8[16384,512] * W1f8[2048,512]^T + b))
__global__ __launch_bounds__(512) void gemm1_f8(
    const f8* __restrict__ A, const f8* __restrict__ Bw,
    const float* __restrict__ bias, f8* __restrict__ C)
{
    const int K = DIM, KT = K / 64;   // 8
    extern __shared__ __align__(16) char dsg1[];
    bf16 (*As)[GBM][SSTR] = (bf16(*)[GBM][SSTR])dsg1;
    bf16 (*Bs)[GBN][SSTR] = (bf16(*)[GBN][SSTR])(dsg1 + G_AS_BYTES);
    int m0 = blockIdx.y * GBM, n0 = blockIdx.x * GBN;
    int tid = threadIdx.x;
    int wid = tid >> 5, lane = tid & 31;
    int wm = (wid & 3) * 64, wn = (wid >> 2) * 32;
    int g = lane >> 2, tg = lane & 3;
    int lrow = (lane & 7) + ((lane >> 3) & 1) * 8;
    int lcol = ((lane >> 4) & 1) * 8;
    float acc[4][4][4];
#pragma unroll
    for (int i = 0; i < 4; i++)
#pragma unroll
        for (int j = 0; j < 4; j++)
#pragma unroll
            for (int k = 0; k < 4; k++) acc[i][j][k] = 0.f;

    int lr = tid >> 1, lcB = (tid & 1) * 32;   // bytes within 64-B row
    const f8* apb = A + (size_t)(m0 + lr) * K + lcB;
    const f8* bpb = Bw + (size_t)(n0 + lr) * K + lcB;   // valid tid<256

    auto load_tile = [&](int kt, int buf) {
        char* da = (char*)&As[buf][lr][0] + lcB;
        const f8* ap = apb + kt * 64;
        cp16(da,      ap);
        cp16(da + 16, ap + 16);
        if (tid < 256) {
            char* db = (char*)&Bs[buf][lr][0] + lcB;
            const f8* bp = bpb + kt * 64;
            cp16(db,      bp);
            cp16(db + 16, bp + 16);
        }
    };

    load_tile(0, 0);
    CP_COMMIT();
    load_tile(1, 1);
    CP_COMMIT();
    load_tile(2, 2);
    CP_COMMIT();
    for (int kt = 0; kt < KT; kt++) {
        int buf = kt & 3;
        if (kt + 2 < KT)      { CP_WAIT(2); }
        else if (kt + 1 < KT) { CP_WAIT(1); }
        else                  { CP_WAIT(0); }
        __syncthreads();
        if (kt + 3 < KT) {
            load_tile(kt + 3, (kt + 3) & 3);
            CP_COMMIT();
        }
#pragma unroll
        for (int ks = 0; ks < 2; ks++) {
            int kb = ks * 16;
            unsigned af[4][4], bb[2][4];
#pragma unroll
            for (int mi = 0; mi < 4; mi++)
                ldmx4(af[mi], &As[buf][wm + mi * 16 + lrow][kb + lcol]);
#pragma unroll
            for (int nh = 0; nh < 2; nh++)
                ldmx4(bb[nh], &Bs[buf][wn + nh * 16 + lrow][kb + lcol]);
#pragma unroll
            for (int mi = 0; mi < 4; mi++)
#pragma unroll
                for (int ni = 0; ni < 4; ni++) {
                    unsigned bfr[2] = { bb[ni >> 1][ni & 1], bb[ni >> 1][(ni & 1) + 2] };
                    mma16832f8(acc[mi][ni], af[mi], bfr);
                }
        }
    }
#pragma unroll
    for (int mi = 0; mi < 4; mi++)
#pragma unroll
        for (int ni = 0; ni < 4; ni++) {
            int col = n0 + wn + ni * 8 + tg * 2;
            float b0 = bias[col], b1 = bias[col + 1];
            int row0 = m0 + wm + mi * 16 + g;
#pragma unroll
            for (int rr = 0; rr < 2; rr++) {
                int r = row0 + rr * 8;
                float2 v;
                v.x = gelu_exact(acc[mi][ni][rr * 2 + 0] + b0);
                v.y = gelu_exact(acc[mi][ni][rr * 2 + 1] + b1);
                __nv_fp8x2_storage_t p = __nv_cvt_float2_to_fp8x2(v, __NV_SATFINITE, __NV_E4M3);
                *(__nv_fp8x2_storage_t*)&C[(size_t)r * FDIM + col] = p;
            }
        }
}

// GEMM2: out = x_in + gamma*(A8[16384,2048]*W2f8[512,2048]^T + b), NCHW epi
__global__ __launch_bounds__(512) void gemm2_f8(
    const f8* __restrict__ A, const f8* __restrict__ Bw,
    const float* __restrict__ bias2, const float* __restrict__ gamma,
    const float* __restrict__ xin, float* __restrict__ out)
{
    const int K = FDIM, KT = K / 64;  // 32
    extern __shared__ __align__(16) char dsg2[];
    bf16 (*As)[GBM][SSTR] = (bf16(*)[GBM][SSTR])dsg2;
    bf16 (*Bs)[GBN][SSTR] = (bf16(*)[GBN][SSTR])(dsg2 + G_AS_BYTES);
    int m0 = blockIdx.y * GBM, n0 = blockIdx.x * GBN;
    int tid = threadIdx.x;
    int wid = tid >> 5, lane = tid & 31;
    int wm = (wid & 3) * 64, wn = (wid >> 2) * 32;
    int g = lane >> 2, tg = lane & 3;
    int lrow = (lane & 7) + ((lane >> 3) & 1) * 8;
    int lcol = ((lane >> 4) & 1) * 8;
    float acc[4][4][4];
#pragma unroll
    for (int i = 0; i < 4; i++)
#pragma unroll
        for (int j = 0; j < 4; j++)
#pragma unroll
            for (int k = 0; k < 4; k++) acc[i][j][k] = 0.f;

    int lr = tid >> 1, lcB = (tid & 1) * 32;
    const f8* apb = A + (size_t)(m0 + lr) * K + lcB;
    const f8* bpb = Bw + (size_t)(n0 + lr) * K + lcB;

    auto load_tile = [&](int kt, int buf) {
        char* da = (char*)&As[buf][lr][0] + lcB;
        const f8* ap = apb + kt * 64;
        cp16(da,      ap);
        cp16(da + 16, ap + 16);
        if (tid < 256) {
            char* db = (char*)&Bs[buf][lr][0] + lcB;
            const f8* bp = bpb + kt * 64;
            cp16(db,      bp);
            cp16(db + 16, bp + 16);
        }
    };

    load_tile(0, 0);
    CP_COMMIT();
    load_tile(1, 1);
    CP_COMMIT();
    load_tile(2, 2);
    CP_COMMIT();
    for (int kt = 0; kt < KT; kt++) {
        int buf = kt & 3;
        if (kt + 2 < KT)      { CP_WAIT(2); }
        else if (kt + 1 < KT) { CP_WAIT(1); }
        else                  { CP_WAIT(0); }
        __syncthreads();
        if (kt + 3 < KT) {
            load_tile(kt + 3, (kt + 3) & 3);
            CP_COMMIT();
        }
#pragma unroll
        for (int ks = 0; ks < 2; ks++) {
            int kb = ks * 16;
            unsigned af[4][4], bb[2][4];
#pragma unroll
            for (int mi = 0; mi < 4; mi++)
                ldmx4(af[mi], &As[buf][wm + mi * 16 + lrow][kb + lcol]);
#pragma unroll
            for (int nh = 0; nh < 2; nh++)
                ldmx4(bb[nh], &Bs[buf][wn + nh * 16 + lrow][kb + lcol]);
#pragma unroll
            for (int mi = 0; mi < 4; mi++)
#pragma unroll
                for (int ni = 0; ni < 4; ni++) {
                    unsigned bfr[2] = { bb[ni >> 1][ni & 1], bb[ni >> 1][(ni & 1) + 2] };
                    mma16832f8(acc[mi][ni], af[mi], bfr);
                }
        }
    }
    __syncthreads();
    // epilogue: 32-col chunks through smem (256 rows) -> coalesced NCHW writes
    float (*sbuf)[33] = (float(*)[33])dsg2;
    int cc = tid >> 4, seg = tid & 15;
#pragma unroll
    for (int nc = 0; nc < 4; nc++) {
        if ((wid >> 2) == nc) {
#pragma unroll
            for (int mi = 0; mi < 4; mi++)
#pragma unroll
                for (int ni = 0; ni < 4; ni++)
#pragma unroll
                    for (int rr = 0; rr < 2; rr++)
#pragma unroll
                        for (int j = 0; j < 2; j++)
                            sbuf[wm + mi * 16 + g + rr * 8][ni * 8 + tg * 2 + j] =
                                acc[mi][ni][rr * 2 + j];
        }
        __syncthreads();
        int col = n0 + nc * 32 + cc;
        float gb = gamma[col], bb2 = bias2[col];
        size_t colbase = ((size_t)(m0 >> 10) * DIM + col) * NPIX + (m0 & 1023);
#pragma unroll
        for (int q = 0; q < 4; q++) {
            int r = q * 64 + seg * 4;
            float4 xv = *(const float4*)&xin[colbase + r];
            float4 o;
            o.x = xv.x + gb * (sbuf[r + 0][cc] + bb2);
            o.y = xv.y + gb * (sbuf[r + 1][cc] + bb2);
            o.z = xv.z + gb * (sbuf[r + 2][cc] + bb2);
            o.w = xv.w + gb * (sbuf[r + 3][cc] + bb2);
            *(float4*)&out[colbase + r] = o;
        }
        __syncthreads();
    }
}

// ---------------- host launcher ----------------
extern "C" void kernel_launch(void* const* d_in, const int* in_sizes, int n_in,
                              void* d_out, int out_size)
{
    const float* x      = (const float*)d_in[0];
    const float* pe_w1  = (const float*)d_in[1];
    const float* pe_bng = (const float*)d_in[2];
    const float* pe_bnb = (const float*)d_in[3];
    const float* pe_bnm = (const float*)d_in[4];
    const float* pe_bnv = (const float*)d_in[5];
    const float* pe_w2  = (const float*)d_in[6];
    const float* pe_b2  = (const float*)d_in[7];
    const float* kg_w1  = (const float*)d_in[8];
    const float* kg_bng = (const float*)d_in[9];
    const float* kg_bnb = (const float*)d_in[10];
    const float* kg_bnm = (const float*)d_in[11];
    const float* kg_bnv = (const float*)d_in[12];
    const float* kg_w2  = (const float*)d_in[13];
    const float* kg_b2  = (const float*)d_in[14];
    const float* bias   = (const float*)d_in[15];
    const float* ln_w   = (const float*)d_in[16];
    const float* ln_b   = (const float*)d_in[17];
    const float* pw1_w  = (const float*)d_in[18];
    const float* pw1_b  = (const float*)d_in[19];
    const float* pw2_w  = (const float*)d_in[20];
    const float* pw2_b  = (const float*)d_in[21];
    const float* gamma  = (const float*)d_in[22];
    float* outp = (float*)d_out;

    bf16 *pxtok, *pxtok2, *phtok, *pkwtok, *py;
    bf16 *pw1pe, *pw1kg, *pw2pe, *pw2kg;
    f8 *pybf8, *pmid8, *pw1f8, *pw2f8;
    cudaGetSymbolAddress((void**)&pxtok,  g_xtok);
    cudaGetSymbolAddress((void**)&pxtok2, g_xtok2);
    cudaGetSymbolAddress((void**)&phtok,  g_htok);
    cudaGetSymbolAddress((void**)&pkwtok, g_kwtok);
    cudaGetSymbolAddress((void**)&py,  g_y);
    cudaGetSymbolAddress((void**)&pybf8, g_ybf8);
    cudaGetSymbolAddress((void**)&pmid8, g_mid8);
    cudaGetSymbolAddress((void**)&pw1f8, g_w1f8);
    cudaGetSymbolAddress((void**)&pw2f8, g_w2f8);
    cudaGetSymbolAddress((void**)&pw1pe, g_w1pe);
    cudaGetSymbolAddress((void**)&pw1kg, g_w1kg);
    cudaGetSymbolAddress((void**)&pw2pe, g_w2pe);
    cudaGetSymbolAddress((void**)&pw2kg, g_w2kg);

    cudaFuncSetAttribute(conv1_tok, cudaFuncAttributeMaxDynamicSharedMemorySize, C1_SMEM);
    cudaFuncSetAttribute(conv2_tok, cudaFuncAttributeMaxDynamicSharedMemorySize, C2_SMEM);
    cudaFuncSetAttribute(gemm1_f8, cudaFuncAttributeMaxDynamicSharedMemorySize, G_SMEM);
    cudaFuncSetAttribute(gemm2_f8, cudaFuncAttributeMaxDynamicSharedMemorySize, G_SMEM);

    cvt_all<<<(FDIM * DIM + 255) / 256, 256>>>(pw1_w, pw2_w, pe_w1, kg_w1, pe_w2, kg_w2,
                                               pw1f8, pw2f8, pw1pe, pw1kg, pw2pe, pw2kg);
    nchw2tok<<<dim3(8, 4, BATCH), 256>>>(x, pxtok);

    conv1_tok<<<NTOK / 64, 512, C1_SMEM>>>(pxtok, pw1pe, pe_bng, pe_bnb, pe_bnm, pe_bnv, phtok);
    conv2_tok<<<dim3(8, NTOK / 128), 256, C2_SMEM>>>(phtok, pw2pe, pe_b2, pxtok, pxtok2);
    conv1_tok<<<NTOK / 64, 512, C1_SMEM>>>(pxtok2, pw1kg, kg_bng, kg_bnb, kg_bnm, kg_bnv, phtok);
    conv2_tok<<<dim3(8, NTOK / 128), 256, C2_SMEM>>>(phtok, pw2kg, kg_b2, nullptr, pkwtok);

    circ_tok<<<(BATCH * DIM) / 4, 256>>>(pxtok2, pkwtok, bias, py);

    ln2_kernel<<<dim3(16, BATCH), 256>>>(py, ln_w, ln_b, pybf8);

    gemm1_f8<<<dim3(FDIM / GBN, NTOK / GBM), 512, G_SMEM>>>(pybf8, pw1f8, pw1_b, pmid8);
    gemm2_f8<<<dim3(DIM / GBN, NTOK / GBM), 512, G_SMEM>>>(pmid8, pw2f8, pw2_b, gamma, x, outp);
}

// round 17
// speedup vs baseline: 1.1882x; 1.0299x over previous
#include <cuda_runtime.h>
#include <cuda_bf16.h>
#include <cuda_fp8.h>
#include <math.h>

#define BATCH 16
#define DIM 512
#define MIDC 32
#define NPIX 1024
#define NTOK 16384
#define FDIM 2048

typedef __nv_bfloat16 bf16;
typedef __nv_fp8_storage_t f8;

// ---------------- scratch (static device memory) ----------------
__device__ f8   g_xtok8 [NTOK * DIM];
__device__ f8   g_xtok28[NTOK * DIM];
__device__ f8   g_htok8 [NTOK * MIDC];
__device__ f8   g_kwtok8[NTOK * DIM];
__device__ bf16 g_y [BATCH * DIM * NPIX];
__device__ f8   g_ybf8[NTOK * DIM];
__device__ f8   g_mid8[NTOK * FDIM];
__device__ f8   g_w1f8[FDIM * DIM];
__device__ f8   g_w2f8[DIM * FDIM];
__device__ f8   g_w1pe8[9 * MIDC * DIM];
__device__ f8   g_w1kg8[9 * MIDC * DIM];
__device__ f8   g_w2pe8[9 * DIM * MIDC];
__device__ f8   g_w2kg8[9 * DIM * MIDC];

// ---------------- helpers ----------------
__device__ __forceinline__ float f8f(f8 v) {
    __half_raw hr = __nv_cvt_fp8_to_halfraw(v, __NV_E4M3);
    return __half2float(*(__half*)&hr);
}
__device__ __forceinline__ f8 ff8(float v) {
    return __nv_cvt_float_to_fp8(v, __NV_SATFINITE, __NV_E4M3);
}
__device__ __forceinline__ void cp16(void* s, const void* g) {
    unsigned sa = (unsigned)__cvta_generic_to_shared(s);
    asm volatile("cp.async.cg.shared.global [%0], [%1], 16;\n" :: "r"(sa), "l"(g));
}
__device__ __forceinline__ void cp16p(void* s, const void* g, bool pred) {
    unsigned sa = (unsigned)__cvta_generic_to_shared(s);
    int sz = pred ? 16 : 0;
    asm volatile("cp.async.cg.shared.global [%0], [%1], 16, %2;\n" :: "r"(sa), "l"(g), "r"(sz));
}
#define CP_COMMIT() asm volatile("cp.async.commit_group;\n")
#define CP_WAIT(n)  asm volatile("cp.async.wait_group %0;\n" :: "n"(n))

__device__ __forceinline__ void ldmx4(unsigned* r, const void* p) {
    unsigned a = (unsigned)__cvta_generic_to_shared(p);
    asm volatile("ldmatrix.sync.aligned.m8n8.x4.shared.b16 {%0,%1,%2,%3}, [%4];\n"
                 : "=r"(r[0]), "=r"(r[1]), "=r"(r[2]), "=r"(r[3]) : "r"(a));
}
__device__ __forceinline__ void mma16832f8(float* d, const unsigned* a, const unsigned* b) {
    asm volatile(
        "mma.sync.aligned.m16n8k32.row.col.f32.e4m3.e4m3.f32 "
        "{%0,%1,%2,%3}, {%4,%5,%6,%7}, {%8,%9}, {%0,%1,%2,%3};\n"
        : "+f"(d[0]), "+f"(d[1]), "+f"(d[2]), "+f"(d[3])
        : "r"(a[0]), "r"(a[1]), "r"(a[2]), "r"(a[3]), "r"(b[0]), "r"(b[1]));
}

// ---------------- merged weight conversion (all fp8) ----------------
__global__ void cvt_all(const float* __restrict__ w1, const float* __restrict__ w2,
                        const float* __restrict__ pw1, const float* __restrict__ kw1,
                        const float* __restrict__ pw2, const float* __restrict__ kw2,
                        f8* __restrict__ o1, f8* __restrict__ o2,
                        f8* __restrict__ o1p, f8* __restrict__ o1k,
                        f8* __restrict__ o2p, f8* __restrict__ o2k)
{
    int i = blockIdx.x * blockDim.x + threadIdx.x;
    if (i < FDIM * DIM) {
        o1[i] = ff8(w1[i]);
        o2[i] = ff8(w2[i]);
    }
    if (i < MIDC * DIM * 9) {
        int off = i % 9;
        int ic = (i / 9) % DIM, oc = i / (9 * DIM);
        o1p[(off * MIDC + oc) * DIM + ic] = ff8(pw1[i]);
        o1k[(off * MIDC + oc) * DIM + ic] = ff8(kw1[i]);
        int ic2 = (i / 9) % MIDC, oc2 = i / (9 * MIDC);
        o2p[(off * DIM + oc2) * MIDC + ic2] = ff8(pw2[i]);
        o2k[(off * DIM + oc2) * MIDC + ic2] = ff8(kw2[i]);
    }
}

// ---------------- NCHW fp32 -> token fp8 transpose ----------------
__global__ __launch_bounds__(256) void nchw2tok(const float* __restrict__ X, f8* __restrict__ T)
{
    __shared__ bf16 sm[128][136];
    int hw0 = blockIdx.x * 128, c0 = blockIdx.y * 128, b = blockIdx.z;
    int tid = threadIdx.x;
    const float* xp = X + ((size_t)b * DIM + c0) * NPIX + hw0;
#pragma unroll
    for (int i = 0; i < 16; i++) {
        int idx = tid + i * 256;
        int rc = idx >> 5, u = idx & 31;
        float4 v = *(const float4*)&xp[(size_t)rc * NPIX + u * 4];
        union { uint2 q; bf16 h[4]; } pk;
        pk.h[0] = __float2bfloat16(v.x); pk.h[1] = __float2bfloat16(v.y);
        pk.h[2] = __float2bfloat16(v.z); pk.h[3] = __float2bfloat16(v.w);
        *(uint2*)&sm[rc][u * 4] = pk.q;
    }
    __syncthreads();
    f8* tp = T + ((size_t)(b * NPIX + hw0)) * DIM + c0;
#pragma unroll
    for (int i = 0; i < 8; i++) {
        int idx = tid + i * 256;
        int rt = idx >> 4, uu = idx & 15;
        union { uint2 q; f8 h[8]; } pk;
#pragma unroll
        for (int j = 0; j < 8; j++)
            pk.h[j] = ff8(__bfloat162float(sm[uu * 8 + j][rt]));
        *(uint2*)&tp[(size_t)rt * DIM + uu * 8] = pk.q;
    }
}

// ---------------- conv1 fp8: 512-thread dual-warpgroup K-split --------------
// M tile 64, N=32, K = 9*512 fp8. 36 iterations of 128 fp8-ch pairs.
#define C1RB 80
#define C1_AS_BYTES (6 * 64 * C1RB)      // 30720
#define C1_BS_BYTES (6 * 32 * C1RB)      // 15360
#define C1_PB_BYTES (8 * 16 * 16 * 4)    // 8192
#define C1_SMEM (C1_AS_BYTES + C1_BS_BYTES + C1_PB_BYTES + 256)
__global__ __launch_bounds__(512) void conv1_tok(
    const f8* __restrict__ X, const f8* __restrict__ W,
    const float* __restrict__ bng, const float* __restrict__ bnb,
    const float* __restrict__ bnm, const float* __restrict__ bnv,
    f8* __restrict__ O)
{
    extern __shared__ __align__(16) char dsm[];
    char* Asb = dsm;
    char* Bsb = dsm + C1_AS_BYTES;
    float (*pbuf)[16][16] = (float(*)[16][16])(dsm + C1_AS_BYTES + C1_BS_BYTES);
    float* sS = (float*)(dsm + C1_AS_BYTES + C1_BS_BYTES + C1_PB_BYTES);
    float* sT = sS + 32;

    int m0 = blockIdx.x * 64;
    int tid = threadIdx.x;
    if (tid < 32) {
        float inv = rsqrtf(bnv[tid] + 1e-5f);
        float s = bng[tid] * inv;
        sS[tid] = s;
        sT[tid] = bnb[tid] - bnm[tid] * s;
    }
    int ar = tid >> 3, aqB = (tid & 7) * 16;
    int asub = aqB >> 6, acolB = aqB & 63;
    int t = m0 + ar;
    int th = (t >> 5) & 31, tw = t & 31;
    int br = (tid & 255) >> 3, bqB = (tid & 7) * 16;
    int bsub = bqB >> 6, bcolB = bqB & 63;
    int wid = tid >> 5, lane = tid & 31;
    int wg = wid >> 3, wl = wid & 7;
    int wm = (wl & 3) * 16, wn = (wl >> 2) * 16;
    int g = lane >> 2, tg = lane & 3;
    int lrow = (lane & 7) + ((lane >> 3) & 1) * 8;
    int lcolB = ((lane >> 4) & 1) * 16;

    float acc[2][4];
#pragma unroll
    for (int i = 0; i < 2; i++)
#pragma unroll
        for (int j = 0; j < 4; j++) acc[i][j] = 0.f;

    auto load_pair = [&](int p, int ds) {
        int off = p >> 2, k0 = (p & 3) * 128;
        int dy = off / 3 - 1, dx = off % 3 - 1;
        bool valid = ((unsigned)(th + dy) < 32u) && ((unsigned)(tw + dx) < 32u);
        const f8* srcA = X + ((long)(t + dy * 32 + dx)) * DIM + k0 + aqB;
        cp16p(Asb + (ds * 2 + asub) * 64 * C1RB + ar * C1RB + acolB, srcA, valid);
        if (tid < 256) {
            const f8* srcB = W + (size_t)(off * MIDC + br) * DIM + k0 + bqB;
            cp16(Bsb + (ds * 2 + bsub) * 32 * C1RB + br * C1RB + bcolB, srcB);
        }
    };

    load_pair(0, 0);
    CP_COMMIT();
    load_pair(1, 1);
    CP_COMMIT();
    for (int p = 0; p < 36; p++) {
        int ds = p % 3;
        if (p + 1 < 36) { CP_WAIT(1); } else { CP_WAIT(0); }
        __syncthreads();
        if (p + 2 < 36) {
            load_pair(p + 2, (p + 2) % 3);
            CP_COMMIT();
        }
        char* Ab = Asb + (ds * 2 + wg) * 64 * C1RB;
        char* Bb = Bsb + (ds * 2 + wg) * 32 * C1RB;
#pragma unroll
        for (int kc = 0; kc < 2; kc++) {
            int kbB = kc * 32;
            unsigned a[4], bb[4];
            ldmx4(a,  Ab + (wm + lrow) * C1RB + kbB + lcolB);
            ldmx4(bb, Bb + (wn + lrow) * C1RB + kbB + lcolB);
            unsigned b0[2] = { bb[0], bb[2] };
            unsigned b1[2] = { bb[1], bb[3] };
            mma16832f8(acc[0], a, b0);
            mma16832f8(acc[1], a, b1);
        }
    }
    if (wg == 1) {
#pragma unroll
        for (int ni = 0; ni < 2; ni++)
#pragma unroll
            for (int rr = 0; rr < 2; rr++)
#pragma unroll
                for (int j = 0; j < 2; j++)
                    pbuf[wl][g + rr * 8][ni * 8 + tg * 2 + j] = acc[ni][rr * 2 + j];
    }
    __syncthreads();
    if (wg == 0) {
#pragma unroll
        for (int ni = 0; ni < 2; ni++)
#pragma unroll
            for (int rr = 0; rr < 2; rr++) {
                int col = wn + ni * 8 + tg * 2;
                int row = wm + g + rr * 8;
                float v0 = acc[ni][rr * 2 + 0] + pbuf[wl][g + rr * 8][ni * 8 + tg * 2 + 0];
                float v1 = acc[ni][rr * 2 + 1] + pbuf[wl][g + rr * 8][ni * 8 + tg * 2 + 1];
                v0 = fmaxf(v0 * sS[col]     + sT[col],     0.f);
                v1 = fmaxf(v1 * sS[col + 1] + sT[col + 1], 0.f);
                union { unsigned short u; f8 h[2]; } pk;
                pk.h[0] = ff8(v0);
                pk.h[1] = ff8(v1);
                *(unsigned short*)&O[(size_t)(m0 + row) * MIDC + col] = pk.u;
            }
    }
}

// ---------------- conv2 fp8: halo-resident, barrier-free --------------------
#define C2RB 48
#define C2_HS_BYTES (6 * 34 * C2RB)      // 9792
#define C2_BS_BYTES (9 * 64 * C2RB)      // 27648
#define C2_SMEM (C2_HS_BYTES + C2_BS_BYTES + 128)
__global__ __launch_bounds__(256) void conv2_tok(
    const f8* __restrict__ Hx, const f8* __restrict__ W,
    const float* __restrict__ b2, const f8* __restrict__ res,
    f8* __restrict__ O)
{
    extern __shared__ __align__(16) char dsm2[];
    char* hsb = dsm2;
    char* bsb = dsm2 + C2_HS_BYTES;
    int n0 = blockIdx.x * 64, m0 = blockIdx.y * 128;
    int b = m0 >> 10;
    int row0 = (m0 >> 5) & 31;
    int tid = threadIdx.x;

    // halo: 6x34 tokens x 32 fp8 = 2 cp16 each (zero-filled borders)
    for (int idx = tid; idx < 408; idx += 256) {
        int pos = idx >> 1, chk = idx & 1;
        int r = pos / 34, c = pos - r * 34;
        int trow = row0 + r - 1, tcol = c - 1;
        bool valid = ((unsigned)trow < 32u) && ((unsigned)tcol < 32u);
        const f8* src = Hx + ((size_t)(b * NPIX + trow * 32 + tcol)) * MIDC + chk * 16;
        cp16p(hsb + (r * 34 + c) * C2RB + chk * 16, src, valid);
    }
    if (tid < 128) {
        int row = tid >> 1, chk = tid & 1;
#pragma unroll
        for (int off = 0; off < 9; off++)
            cp16(bsb + (off * 64 + row) * C2RB + chk * 16,
                 &W[(size_t)(off * DIM + n0 + row) * MIDC + chk * 16]);
    }
    CP_COMMIT();
    CP_WAIT(0);
    __syncthreads();

    int wid = tid >> 5, lane = tid & 31;
    int wm = (wid & 3) * 32, wn = (wid >> 2) * 32;
    int g = lane >> 2, tg = lane & 3;
    int lrow = (lane & 7) + ((lane >> 3) & 1) * 8;
    int lcolB = ((lane >> 4) & 1) * 16;

    float acc[2][4][4];
#pragma unroll
    for (int i = 0; i < 2; i++)
#pragma unroll
        for (int j = 0; j < 4; j++)
#pragma unroll
            for (int k = 0; k < 4; k++) acc[i][j][k] = 0.f;

    const char* abase[2];
#pragma unroll
    for (int mi = 0; mi < 2; mi++) {
        int tok = wm + mi * 16 + lrow;
        int tr = tok >> 5, tc = tok & 31;
        abase[mi] = hsb + ((tr + 1) * 34 + (tc + 1)) * C2RB + lcolB;
    }

#pragma unroll
    for (int off = 0; off < 9; off++) {
        int dy = off / 3 - 1, dx = off % 3 - 1;
        int shift = (dy * 34 + dx) * C2RB;
        unsigned a[2][4], bb[2][4];
#pragma unroll
        for (int mi = 0; mi < 2; mi++)
            ldmx4(a[mi], abase[mi] + shift);
#pragma unroll
        for (int nh = 0; nh < 2; nh++)
            ldmx4(bb[nh], bsb + (off * 64 + wn + nh * 16 + lrow) * C2RB + lcolB);
#pragma unroll
        for (int mi = 0; mi < 2; mi++)
#pragma unroll
            for (int ni = 0; ni < 4; ni++) {
                unsigned bfr[2] = { bb[ni >> 1][ni & 1], bb[ni >> 1][(ni & 1) + 2] };
                mma16832f8(acc[mi][ni], a[mi], bfr);
            }
    }
    float bv0[4], bv1[4];
#pragma unroll
    for (int ni = 0; ni < 4; ni++) {
        int col = n0 + wn + ni * 8 + tg * 2;
        bv0[ni] = b2[col];
        bv1[ni] = b2[col + 1];
    }
#pragma unroll
    for (int mi = 0; mi < 2; mi++)
#pragma unroll
        for (int ni = 0; ni < 4; ni++)
#pragma unroll
            for (int rr = 0; rr < 2; rr++) {
                int row = m0 + wm + mi * 16 + g + rr * 8;
                size_t ad = (size_t)row * DIM + n0 + wn + ni * 8 + tg * 2;
                float v0 = acc[mi][ni][rr * 2 + 0] + bv0[ni];
                float v1 = acc[mi][ni][rr * 2 + 1] + bv1[ni];
                if (res) {
                    union { unsigned short u; f8 h[2]; } rv;
                    rv.u = *(const unsigned short*)&res[ad];
                    v0 += f8f(rv.h[0]);
                    v1 += f8f(rv.h[1]);
                }
                union { unsigned short u; f8 h[2]; } pk;
                pk.h[0] = ff8(v0);
                pk.h[1] = ff8(v1);
                *(unsigned short*)&O[ad] = pk.u;
            }
}

// ---------------- circ: fp8 tokens in, bf16 y out ---------------------------
__global__ __launch_bounds__(256) void circ_tok(
    const f8* __restrict__ Xt, const f8* __restrict__ KWt,
    const float* __restrict__ bias, bf16* __restrict__ y)
{
    __shared__ float xs[4][32][36];
    __shared__ float ks[4][32][36];
    __shared__ float kv[4][32];
    int p0 = blockIdx.x * 4;
    int b = p0 >> 9;
    int c0 = p0 & 511;
    int tid = threadIdx.x;
    int lp = tid >> 6, lt = tid & 63;
    int c = c0 + lp;

#pragma unroll
    for (int i = 0; i < 4; i++) {
        int tok = tid + i * 256;
        int hh = tok >> 5, ww = tok & 31;
        size_t base = (size_t)(b * NPIX + tok) * DIM + c0;
        union { unsigned u; f8 h[4]; } xv, kw;
        xv.u = *(const unsigned*)&Xt[base];
        kw.u = *(const unsigned*)&KWt[base];
#pragma unroll
        for (int q = 0; q < 4; q++) {
            xs[q][hh][ww] = f8f(xv.h[q]);
            ks[q][hh][ww] = f8f(kw.h[q]);
        }
    }
    __syncthreads();
    if (lt < 32) {
        float s = 0.f;
        if (c < 256) {
#pragma unroll
            for (int ww = 0; ww < 32; ww++) s += ks[lp][lt][ww];
        } else {
#pragma unroll
            for (int hh = 0; hh < 32; hh++) s += ks[lp][hh][lt];
        }
        kv[lp][lt] = s * (1.f / 32.f);
    }
    __syncthreads();

    int t_r = (lt >> 3) * 4;
    int t_c = (lt & 7) * 4;
    float acc[4][4];
#pragma unroll
    for (int r = 0; r < 4; r++)
#pragma unroll
        for (int cc2 = 0; cc2 < 4; cc2++) acc[r][cc2] = 0.f;
    float bv = bias[c];

    if (c < 256) {
        float kr[32];
#pragma unroll
        for (int u = 0; u < 32; u++) kr[u] = kv[lp][(u - t_r) & 31];
#pragma unroll
        for (int j = 0; j < 32; j++) {
            float4 xv = *(const float4*)&xs[lp][j][t_c];
#pragma unroll
            for (int ri = 0; ri < 4; ri++) {
                float kk = kr[(j - ri) & 31];
                acc[ri][0] += kk * xv.x;
                acc[ri][1] += kk * xv.y;
                acc[ri][2] += kk * xv.z;
                acc[ri][3] += kk * xv.w;
            }
        }
    } else {
        float kr[32];
#pragma unroll
        for (int u = 0; u < 32; u++) kr[u] = kv[lp][(u - t_c) & 31];
#pragma unroll
        for (int j = 0; j < 32; j++) {
            float xv[4];
#pragma unroll
            for (int ri = 0; ri < 4; ri++) xv[ri] = xs[lp][t_r + ri][j];
#pragma unroll
            for (int ci = 0; ci < 4; ci++) {
                float kk = kr[(j - ci) & 31];
#pragma unroll
                for (int ri = 0; ri < 4; ri++) acc[ri][ci] += kk * xv[ri];
            }
        }
    }
    bf16* yp = y + (size_t)(p0 + lp) * NPIX;
#pragma unroll
    for (int ri = 0; ri < 4; ri++) {
        union { uint2 q; bf16 h[4]; } pk;
        pk.h[0] = __float2bfloat16(acc[ri][0] + bv);
        pk.h[1] = __float2bfloat16(acc[ri][1] + bv);
        pk.h[2] = __float2bfloat16(acc[ri][2] + bv);
        pk.h[3] = __float2bfloat16(acc[ri][3] + bv);
        *(uint2*)&yp[(t_r + ri) * 32 + t_c] = pk.q;
    }
}

// ---------------- LayerNorm: bf16 NCHW in, fp8 tokens out -------------------
__global__ __launch_bounds__(256) void ln2_kernel(
    const bf16* __restrict__ Y, const float* __restrict__ lnw,
    const float* __restrict__ lnb, f8* __restrict__ O)
{
    __shared__ float red[256], red2[256];
    __shared__ float mus[64], rss[64];
    int chunk = blockIdx.x, b = blockIdx.y;
    int hw0 = chunk * 64;
    int tid = threadIdx.x;
    int j = tid & 63, q = tid >> 6;
    const bf16* yb = Y + (size_t)b * DIM * NPIX + hw0 + j;
    float s = 0.f, s2 = 0.f;
    for (int c = q * 128; c < q * 128 + 128; c++) {
        float v = __bfloat162float(yb[(size_t)c * NPIX]);
        s += v; s2 += v * v;
    }
    red[tid] = s; red2[tid] = s2;
    __syncthreads();
    if (tid < 64) {
        float S = red[tid] + red[tid + 64] + red[tid + 128] + red[tid + 192];
        float S2 = red2[tid] + red2[tid + 64] + red2[tid + 128] + red2[tid + 192];
        float mu = S * (1.f / 512.f);
        float var = S2 * (1.f / 512.f) - mu * mu;
        mus[tid] = mu;
        rss[tid] = rsqrtf(var + 1e-6f);
    }
    __syncthreads();
    float mu = mus[j], rstd = rss[j];
    size_t t0 = (size_t)b * NPIX + hw0;
    for (int c8 = q * 128; c8 < q * 128 + 128; c8 += 8) {
        union { uint2 u; f8 h[8]; } pk;
#pragma unroll
        for (int i = 0; i < 8; i++) {
            int c = c8 + i;
            float v = __bfloat162float(yb[(size_t)c * NPIX]);
            pk.h[i] = ff8((v - mu) * rstd * __ldg(&lnw[c]) + __ldg(&lnb[c]));
        }
        *(uint2*)&O[(t0 + j) * DIM + c8] = pk.u;
    }
}

__device__ __forceinline__ float gelu_exact(float x) {
    return 0.5f * x * (1.f + erff(x * 0.70710678118654752f));
}

// ---- FP8 MLP GEMMs: BM=256, BN=128, BK=64 fp8, 512 threads, 4-stage --------
#define GBM 256
#define GBN 128
#define SSTR 40
#define G_AS_BYTES (4 * GBM * SSTR * 2)
#define G_BS_BYTES (4 * GBN * SSTR * 2)
#define G_SMEM (G_AS_BYTES + G_BS_BYTES)

__global__ __launch_bounds__(512) void gemm1_f8(
    const f8* __restrict__ A, const f8* __restrict__ Bw,
    const float* __restrict__ bias, f8* __restrict__ C)
{
    const int K = DIM, KT = K / 64;
    extern __shared__ __align__(16) char dsg1[];
    bf16 (*As)[GBM][SSTR] = (bf16(*)[GBM][SSTR])dsg1;
    bf16 (*Bs)[GBN][SSTR] = (bf16(*)[GBN][SSTR])(dsg1 + G_AS_BYTES);
    int m0 = blockIdx.y * GBM, n0 = blockIdx.x * GBN;
    int tid = threadIdx.x;
    int wid = tid >> 5, lane = tid & 31;
    int wm = (wid & 3) * 64, wn = (wid >> 2) * 32;
    int g = lane >> 2, tg = lane & 3;
    int lrow = (lane & 7) + ((lane >> 3) & 1) * 8;
    int lcol = ((lane >> 4) & 1) * 8;
    float acc[4][4][4];
#pragma unroll
    for (int i = 0; i < 4; i++)
#pragma unroll
        for (int j = 0; j < 4; j++)
#pragma unroll
            for (int k = 0; k < 4; k++) acc[i][j][k] = 0.f;

    int lr = tid >> 1, lcB = (tid & 1) * 32;
    const f8* apb = A + (size_t)(m0 + lr) * K + lcB;
    const f8* bpb = Bw + (size_t)(n0 + lr) * K + lcB;

    auto load_tile = [&](int kt, int buf) {
        char* da = (char*)&As[buf][lr][0] + lcB;
        const f8* ap = apb + kt * 64;
        cp16(da,      ap);
        cp16(da + 16, ap + 16);
        if (tid < 256) {
            char* db = (char*)&Bs[buf][lr][0] + lcB;
            const f8* bp = bpb + kt * 64;
            cp16(db,      bp);
            cp16(db + 16, bp + 16);
        }
    };

    load_tile(0, 0);
    CP_COMMIT();
    load_tile(1, 1);
    CP_COMMIT();
    load_tile(2, 2);
    CP_COMMIT();
    for (int kt = 0; kt < KT; kt++) {
        int buf = kt & 3;
        if (kt + 2 < KT)      { CP_WAIT(2); }
        else if (kt + 1 < KT) { CP_WAIT(1); }
        else                  { CP_WAIT(0); }
        __syncthreads();
        if (kt + 3 < KT) {
            load_tile(kt + 3, (kt + 3) & 3);
            CP_COMMIT();
        }
#pragma unroll
        for (int ks = 0; ks < 2; ks++) {
            int kb = ks * 16;
            unsigned af[4][4], bb[2][4];
#pragma unroll
            for (int mi = 0; mi < 4; mi++)
                ldmx4(af[mi], &As[buf][wm + mi * 16 + lrow][kb + lcol]);
#pragma unroll
            for (int nh = 0; nh < 2; nh++)
                ldmx4(bb[nh], &Bs[buf][wn + nh * 16 + lrow][kb + lcol]);
#pragma unroll
            for (int mi = 0; mi < 4; mi++)
#pragma unroll
                for (int ni = 0; ni < 4; ni++) {
                    unsigned bfr[2] = { bb[ni >> 1][ni & 1], bb[ni >> 1][(ni & 1) + 2] };
                    mma16832f8(acc[mi][ni], af[mi], bfr);
                }
        }
    }
#pragma unroll
    for (int mi = 0; mi < 4; mi++)
#pragma unroll
        for (int ni = 0; ni < 4; ni++) {
            int col = n0 + wn + ni * 8 + tg * 2;
            float b0 = bias[col], b1 = bias[col + 1];
            int row0 = m0 + wm + mi * 16 + g;
#pragma unroll
            for (int rr = 0; rr < 2; rr++) {
                int r = row0 + rr * 8;
                float2 v;
                v.x = gelu_exact(acc[mi][ni][rr * 2 + 0] + b0);
                v.y = gelu_exact(acc[mi][ni][rr * 2 + 1] + b1);
                __nv_fp8x2_storage_t p = __nv_cvt_float2_to_fp8x2(v, __NV_SATFINITE, __NV_E4M3);
                *(__nv_fp8x2_storage_t*)&C[(size_t)r * FDIM + col] = p;
            }
        }
}

__global__ __launch_bounds__(512) void gemm2_f8(
    const f8* __restrict__ A, const f8* __restrict__ Bw,
    const float* __restrict__ bias2, const float* __restrict__ gamma,
    const float* __restrict__ xin, float* __restrict__ out)
{
    const int K = FDIM, KT = K / 64;
    extern __shared__ __align__(16) char dsg2[];
    bf16 (*As)[GBM][SSTR] = (bf16(*)[GBM][SSTR])dsg2;
    bf16 (*Bs)[GBN][SSTR] = (bf16(*)[GBN][SSTR])(dsg2 + G_AS_BYTES);
    int m0 = blockIdx.y * GBM, n0 = blockIdx.x * GBN;
    int tid = threadIdx.x;
    int wid = tid >> 5, lane = tid & 31;
    int wm = (wid & 3) * 64, wn = (wid >> 2) * 32;
    int g = lane >> 2, tg = lane & 3;
    int lrow = (lane & 7) + ((lane >> 3) & 1) * 8;
    int lcol = ((lane >> 4) & 1) * 8;
    float acc[4][4][4];
#pragma unroll
    for (int i = 0; i < 4; i++)
#pragma unroll
        for (int j = 0; j < 4; j++)
#pragma unroll
            for (int k = 0; k < 4; k++) acc[i][j][k] = 0.f;

    int lr = tid >> 1, lcB = (tid & 1) * 32;
    const f8* apb = A + (size_t)(m0 + lr) * K + lcB;
    const f8* bpb = Bw + (size_t)(n0 + lr) * K + lcB;

    auto load_tile = [&](int kt, int buf) {
        char* da = (char*)&As[buf][lr][0] + lcB;
        const f8* ap = apb + kt * 64;
        cp16(da,      ap);
        cp16(da + 16, ap + 16);
        if (tid < 256) {
            char* db = (char*)&Bs[buf][lr][0] + lcB;
            const f8* bp = bpb + kt * 64;
            cp16(db,      bp);
            cp16(db + 16, bp + 16);
        }
    };

    load_tile(0, 0);
    CP_COMMIT();
    load_tile(1, 1);
    CP_COMMIT();
    load_tile(2, 2);
    CP_COMMIT();
    for (int kt = 0; kt < KT; kt++) {
        int buf = kt & 3;
        if (kt + 2 < KT)      { CP_WAIT(2); }
        else if (kt + 1 < KT) { CP_WAIT(1); }
        else                  { CP_WAIT(0); }
        __syncthreads();
        if (kt + 3 < KT) {
            load_tile(kt + 3, (kt + 3) & 3);
            CP_COMMIT();
        }
#pragma unroll
        for (int ks = 0; ks < 2; ks++) {
            int kb = ks * 16;
            unsigned af[4][4], bb[2][4];
#pragma unroll
            for (int mi = 0; mi < 4; mi++)
                ldmx4(af[mi], &As[buf][wm + mi * 16 + lrow][kb + lcol]);
#pragma unroll
            for (int nh = 0; nh < 2; nh++)
                ldmx4(bb[nh], &Bs[buf][wn + nh * 16 + lrow][kb + lcol]);
#pragma unroll
            for (int mi = 0; mi < 4; mi++)
#pragma unroll
                for (int ni = 0; ni < 4; ni++) {
                    unsigned bfr[2] = { bb[ni >> 1][ni & 1], bb[ni >> 1][(ni & 1) + 2] };
                    mma16832f8(acc[mi][ni], af[mi], bfr);
                }
        }
    }
    __syncthreads();
    float (*sbuf)[33] = (float(*)[33])dsg2;
    int cc = tid >> 4, seg = tid & 15;
#pragma unroll
    for (int nc = 0; nc < 4; nc++) {
        if ((wid >> 2) == nc) {
#pragma unroll
            for (int mi = 0; mi < 4; mi++)
#pragma unroll
                for (int ni = 0; ni < 4; ni++)
#pragma unroll
                    for (int rr = 0; rr < 2; rr++)
#pragma unroll
                        for (int j = 0; j < 2; j++)
                            sbuf[wm + mi * 16 + g + rr * 8][ni * 8 + tg * 2 + j] =
                                acc[mi][ni][rr * 2 + j];
        }
        __syncthreads();
        int col = n0 + nc * 32 + cc;
        float gb = gamma[col], bb2 = bias2[col];
        size_t colbase = ((size_t)(m0 >> 10) * DIM + col) * NPIX + (m0 & 1023);
#pragma unroll
        for (int q = 0; q < 4; q++) {
            int r = q * 64 + seg * 4;
            float4 xv = *(const float4*)&xin[colbase + r];
            float4 o;
            o.x = xv.x + gb * (sbuf[r + 0][cc] + bb2);
            o.y = xv.y + gb * (sbuf[r + 1][cc] + bb2);
            o.z = xv.z + gb * (sbuf[r + 2][cc] + bb2);
            o.w = xv.w + gb * (sbuf[r + 3][cc] + bb2);
            *(float4*)&out[colbase + r] = o;
        }
        __syncthreads();
    }
}

// ---------------- host launcher ----------------
extern "C" void kernel_launch(void* const* d_in, const int* in_sizes, int n_in,
                              void* d_out, int out_size)
{
    const float* x      = (const float*)d_in[0];
    const float* pe_w1  = (const float*)d_in[1];
    const float* pe_bng = (const float*)d_in[2];
    const float* pe_bnb = (const float*)d_in[3];
    const float* pe_bnm = (const float*)d_in[4];
    const float* pe_bnv = (const float*)d_in[5];
    const float* pe_w2  = (const float*)d_in[6];
    const float* pe_b2  = (const float*)d_in[7];
    const float* kg_w1  = (const float*)d_in[8];
    const float* kg_bng = (const float*)d_in[9];
    const float* kg_bnb = (const float*)d_in[10];
    const float* kg_bnm = (const float*)d_in[11];
    const float* kg_bnv = (const float*)d_in[12];
    const float* kg_w2  = (const float*)d_in[13];
    const float* kg_b2  = (const float*)d_in[14];
    const float* bias   = (const float*)d_in[15];
    const float* ln_w   = (const float*)d_in[16];
    const float* ln_b   = (const float*)d_in[17];
    const float* pw1_w  = (const float*)d_in[18];
    const float* pw1_b  = (const float*)d_in[19];
    const float* pw2_w  = (const float*)d_in[20];
    const float* pw2_b  = (const float*)d_in[21];
    const float* gamma  = (const float*)d_in[22];
    float* outp = (float*)d_out;

    bf16 *py;
    f8 *pxtok8, *pxtok28, *phtok8, *pkwtok8, *pybf8, *pmid8, *pw1f8, *pw2f8;
    f8 *pw1pe8, *pw1kg8, *pw2pe8, *pw2kg8;
    cudaGetSymbolAddress((void**)&pxtok8,  g_xtok8);
    cudaGetSymbolAddress((void**)&pxtok28, g_xtok28);
    cudaGetSymbolAddress((void**)&phtok8,  g_htok8);
    cudaGetSymbolAddress((void**)&pkwtok8, g_kwtok8);
    cudaGetSymbolAddress((void**)&py,  g_y);
    cudaGetSymbolAddress((void**)&pybf8, g_ybf8);
    cudaGetSymbolAddress((void**)&pmid8, g_mid8);
    cudaGetSymbolAddress((void**)&pw1f8, g_w1f8);
    cudaGetSymbolAddress((void**)&pw2f8, g_w2f8);
    cudaGetSymbolAddress((void**)&pw1pe8, g_w1pe8);
    cudaGetSymbolAddress((void**)&pw1kg8, g_w1kg8);
    cudaGetSymbolAddress((void**)&pw2pe8, g_w2pe8);
    cudaGetSymbolAddress((void**)&pw2kg8, g_w2kg8);

    cudaFuncSetAttribute(conv1_tok, cudaFuncAttributeMaxDynamicSharedMemorySize, C1_SMEM);
    cudaFuncSetAttribute(conv2_tok, cudaFuncAttributeMaxDynamicSharedMemorySize, C2_SMEM);
    cudaFuncSetAttribute(gemm1_f8, cudaFuncAttributeMaxDynamicSharedMemorySize, G_SMEM);
    cudaFuncSetAttribute(gemm2_f8, cudaFuncAttributeMaxDynamicSharedMemorySize, G_SMEM);

    cvt_all<<<(FDIM * DIM + 255) / 256, 256>>>(pw1_w, pw2_w, pe_w1, kg_w1, pe_w2, kg_w2,
                                               pw1f8, pw2f8, pw1pe8, pw1kg8, pw2pe8, pw2kg8);
    nchw2tok<<<dim3(8, 4, BATCH), 256>>>(x, pxtok8);

    conv1_tok<<<NTOK / 64, 512, C1_SMEM>>>(pxtok8, pw1pe8, pe_bng, pe_bnb, pe_bnm, pe_bnv, phtok8);
    conv2_tok<<<dim3(8, NTOK / 128), 256, C2_SMEM>>>(phtok8, pw2pe8, pe_b2, pxtok8, pxtok28);
    conv1_tok<<<NTOK / 64, 512, C1_SMEM>>>(pxtok28, pw1kg8, kg_bng, kg_bnb, kg_bnm, kg_bnv, phtok8);
    conv2_tok<<<dim3(8, NTOK / 128), 256, C2_SMEM>>>(phtok8, pw2kg8, kg_b2, nullptr, pkwtok8);

    circ_tok<<<(BATCH * DIM) / 4, 256>>>(pxtok28, pkwtok8, bias, py);

    ln2_kernel<<<dim3(16, BATCH), 256>>>(py, ln_w, ln_b, pybf8);

    gemm1_f8<<<dim3(FDIM / GBN, NTOK / GBM), 512, G_SMEM>>>(pybf8, pw1f8, pw1_b, pmid8);
    gemm2_f8<<<dim3(DIM / GBN, NTOK / GBM), 512, G_SMEM>>>(pmid8, pw2f8, pw2_b, gamma, x, outp);
}